// round 9
// baseline (speedup 1.0000x reference)
#include <cuda_runtime.h>
#include <cstdint>

// ---------------- problem constants ------------------------------------------
#define NMAX   100000
#define EMAX   1600000
#define DIN    128
#define DH     128
#define DOUT   64
#define NREL   3
#define NPAIR  6                     // (layer, relation) pairs
#define SCAN_CHUNK 1024              // elements per scan block
#define MAXBLK 128                   // >= ceil(NMAX/SCAN_CHUNK) = 98

// ---------------- scratch (__device__ globals; no allocation allowed) --------
__device__ float g_z[(size_t)NMAX * DIN];          // per-relation z = h @ W (scaled)
__device__ float g_h[(size_t)NMAX * DH];           // layer-1 accumulator
__device__ int   g_degi[12 * NMAX];                // int degrees: (pair,dir)
__device__ float g_degf[12 * NMAX];                // rsqrt(clamp(deg,1))
__device__ int   g_off [NPAIR * NMAX];             // CSR offsets (by dst) per pair
__device__ int   g_cnt [NPAIR * NMAX];             // fill tickets
__device__ int   g_adj [(size_t)NPAIR * EMAX];     // src ids grouped by dst
__device__ int   g_bsum[NPAIR * MAXBLK];           // scan block partials

// ---------------- degree counting (int), grid.y = pair -----------------------
__global__ void count_deg_kernel(const int* __restrict__ ei, int* __restrict__ degi,
                                 int E, int M) {
    int p = blockIdx.y;
    int e = blockIdx.x * blockDim.x + threadIdx.x;
    if (e >= E) return;
    int s = __ldg(ei + (size_t)(p * 2 + 0) * E + e);
    int d = __ldg(ei + (size_t)(p * 2 + 1) * E + e);
    atomicAdd(degi + (size_t)(p * 2 + 0) * M + s, 1);
    atomicAdd(degi + (size_t)(p * 2 + 1) * M + d, 1);
}

__global__ void rsqrt_kernel(const int* __restrict__ degi, float* __restrict__ degf, int n) {
    int i = blockIdx.x * blockDim.x + threadIdx.x;
    if (i < n) degf[i] = rsqrtf((float)max(degi[i], 1));
}

// ---------------- exclusive scan of in-degrees -> CSR offsets ----------------
// Phase A: per-chunk exclusive scan + block totals.
__global__ __launch_bounds__(256)
void scanA(const int* __restrict__ degi, int* __restrict__ off,
           int* __restrict__ bsum, int M) {
    int p = blockIdx.y;
    const int* deg = degi + (size_t)(p * 2 + 1) * M;   // in-degree array of pair p
    int* o = off + (size_t)p * M;
    int base = blockIdx.x * SCAN_CHUNK;
    int tid = threadIdx.x;

    int v[4];
    int t = 0;
    #pragma unroll
    for (int k = 0; k < 4; k++) {
        int idx = base + tid * 4 + k;
        v[k] = (idx < M) ? deg[idx] : 0;
        t += v[k];
    }
    __shared__ int sm[256];
    sm[tid] = t;
    __syncthreads();
    #pragma unroll
    for (int ofs = 1; ofs < 256; ofs <<= 1) {
        int u = (tid >= ofs) ? sm[tid - ofs] : 0;
        __syncthreads();
        sm[tid] += u;
        __syncthreads();
    }
    int ex = sm[tid] - t;            // exclusive prefix of this thread's 4-group
    int run = ex;
    #pragma unroll
    for (int k = 0; k < 4; k++) {
        int idx = base + tid * 4 + k;
        if (idx < M) o[idx] = run;
        run += v[k];
    }
    if (tid == 255) bsum[p * MAXBLK + blockIdx.x] = sm[255];
}

// Phase B: exclusive scan of block totals (one block per pair).
__global__ __launch_bounds__(MAXBLK)
void scanB(int* __restrict__ bsum, int nblk) {
    int p = blockIdx.x;
    int tid = threadIdx.x;
    int* b = bsum + p * MAXBLK;
    int t = (tid < nblk) ? b[tid] : 0;
    __shared__ int sm[MAXBLK];
    sm[tid] = t;
    __syncthreads();
    #pragma unroll
    for (int ofs = 1; ofs < MAXBLK; ofs <<= 1) {
        int u = (tid >= ofs) ? sm[tid - ofs] : 0;
        __syncthreads();
        sm[tid] += u;
        __syncthreads();
    }
    if (tid < nblk) b[tid] = sm[tid] - t;
}

// Phase C: add scanned block bases.
__global__ void scanC(int* __restrict__ off, const int* __restrict__ bsum, int M) {
    int p = blockIdx.y;
    int i = blockIdx.x * blockDim.x + threadIdx.x;
    if (i < M) off[(size_t)p * M + i] += bsum[p * MAXBLK + (i >> 10)];
}

// ---------------- CSR fill: adj grouped by dst --------------------------------
__global__ void fill_adj_kernel(const int* __restrict__ ei, const int* __restrict__ off,
                                int* __restrict__ cnt, int* __restrict__ adj,
                                int E, int M) {
    int p = blockIdx.y;
    int e = blockIdx.x * blockDim.x + threadIdx.x;
    if (e >= E) return;
    int s = __ldg(ei + (size_t)(p * 2 + 0) * E + e);
    int d = __ldg(ei + (size_t)(p * 2 + 1) * E + e);
    int pos = atomicAdd(cnt + (size_t)p * M + d, 1);
    adj[(size_t)p * E + off[(size_t)p * M + d] + pos] = s;
}

// ---------------- tiled fp32 GEMM with fused row scaling ---------------------
template<int BN, int TN>
__global__ __launch_bounds__(256)
void gemm_rowscale(const float* __restrict__ A, const float* __restrict__ B,
                   const float* __restrict__ rs, float* __restrict__ C, int M) {
    constexpr int BM = 128;
    constexpr int BK = 32;
    __shared__ float Xs[BM][BK + 1];
    __shared__ float Ws[BK][BN];

    const int tid = threadIdx.x;
    const int tx = tid & 15;
    const int ty = tid >> 4;
    const int row0 = blockIdx.x * BM;

    float acc[8][TN];
    #pragma unroll
    for (int i = 0; i < 8; i++)
        #pragma unroll
        for (int j = 0; j < TN; j++) acc[i][j] = 0.f;

    for (int kt = 0; kt < 128; kt += BK) {
        #pragma unroll
        for (int i = 0; i < 4; i++) {
            int slot = tid + i * 256;
            int r  = slot >> 3;
            int c4 = (slot & 7) * 4;
            float4 v = make_float4(0.f, 0.f, 0.f, 0.f);
            int gr = row0 + r;
            if (gr < M) v = *reinterpret_cast<const float4*>(A + (size_t)gr * 128 + kt + c4);
            Xs[r][c4 + 0] = v.x; Xs[r][c4 + 1] = v.y;
            Xs[r][c4 + 2] = v.z; Xs[r][c4 + 3] = v.w;
        }
        constexpr int BSLOTS = BK * BN / 4;
        #pragma unroll
        for (int i = 0; i < BSLOTS / 256; i++) {
            int slot = tid + i * 256;
            int r  = slot / (BN / 4);
            int c4 = (slot % (BN / 4)) * 4;
            *reinterpret_cast<float4*>(&Ws[r][c4]) =
                *reinterpret_cast<const float4*>(B + (size_t)(kt + r) * BN + c4);
        }
        __syncthreads();

        #pragma unroll
        for (int kk = 0; kk < BK; kk++) {
            float a[8], b[TN];
            #pragma unroll
            for (int i = 0; i < 8; i++) a[i] = Xs[ty * 8 + i][kk];
            #pragma unroll
            for (int jb = 0; jb < TN / 4; jb++) {
                float4 bv = *reinterpret_cast<const float4*>(&Ws[kk][jb * 64 + tx * 4]);
                b[jb * 4 + 0] = bv.x; b[jb * 4 + 1] = bv.y;
                b[jb * 4 + 2] = bv.z; b[jb * 4 + 3] = bv.w;
            }
            #pragma unroll
            for (int i = 0; i < 8; i++)
                #pragma unroll
                for (int j = 0; j < TN; j++) acc[i][j] += a[i] * b[j];
        }
        __syncthreads();
    }

    #pragma unroll
    for (int i = 0; i < 8; i++) {
        int gr = row0 + ty * 8 + i;
        if (gr >= M) continue;
        float s = __ldg(rs + gr);
        #pragma unroll
        for (int jb = 0; jb < TN / 4; jb++) {
            float4 v = make_float4(acc[i][jb * 4 + 0] * s, acc[i][jb * 4 + 1] * s,
                                   acc[i][jb * 4 + 2] * s, acc[i][jb * 4 + 3] * s);
            *reinterpret_cast<float4*>(C + (size_t)gr * BN + jb * 64 + tx * 4) = v;
        }
    }
}

// ---------------- CSR gather aggregation --------------------------------------
// 128-wide: one warp per dst; lane owns float4. out[d] += rs_in[d] * sum z[src].
__global__ __launch_bounds__(256)
void gather128(const float* __restrict__ z, float* __restrict__ out,
               const int* __restrict__ off, const int* __restrict__ degin,
               const int* __restrict__ adj, const float* __restrict__ rsin, int M) {
    int w = (blockIdx.x * blockDim.x + threadIdx.x) >> 5;
    if (w >= M) return;
    int lane = threadIdx.x & 31;
    int st = __ldg(off + w);
    int len = __ldg(degin + w);
    float4 acc = make_float4(0.f, 0.f, 0.f, 0.f);
    int j = 0;
    for (; j + 1 < len; j += 2) {            // 2-deep unroll for MLP
        int s0 = __ldg(adj + st + j);
        int s1 = __ldg(adj + st + j + 1);
        float4 v0 = __ldg(reinterpret_cast<const float4*>(z + (size_t)s0 * 128 + lane * 4));
        float4 v1 = __ldg(reinterpret_cast<const float4*>(z + (size_t)s1 * 128 + lane * 4));
        acc.x += v0.x + v1.x; acc.y += v0.y + v1.y;
        acc.z += v0.z + v1.z; acc.w += v0.w + v1.w;
    }
    if (j < len) {
        int s0 = __ldg(adj + st + j);
        float4 v0 = __ldg(reinterpret_cast<const float4*>(z + (size_t)s0 * 128 + lane * 4));
        acc.x += v0.x; acc.y += v0.y; acc.z += v0.z; acc.w += v0.w;
    }
    float c = __ldg(rsin + w);
    float4* hp = reinterpret_cast<float4*>(out + (size_t)w * 128 + lane * 4);
    float4 cur = *hp;
    cur.x += c * acc.x; cur.y += c * acc.y;
    cur.z += c * acc.z; cur.w += c * acc.w;
    *hp = cur;
}

// 64-wide: one warp per dst; lane owns float2.
__global__ __launch_bounds__(256)
void gather64(const float* __restrict__ z, float* __restrict__ out,
              const int* __restrict__ off, const int* __restrict__ degin,
              const int* __restrict__ adj, const float* __restrict__ rsin, int M) {
    int w = (blockIdx.x * blockDim.x + threadIdx.x) >> 5;
    if (w >= M) return;
    int lane = threadIdx.x & 31;
    int st = __ldg(off + w);
    int len = __ldg(degin + w);
    float2 acc = make_float2(0.f, 0.f);
    int j = 0;
    for (; j + 1 < len; j += 2) {
        int s0 = __ldg(adj + st + j);
        int s1 = __ldg(adj + st + j + 1);
        float2 v0 = __ldg(reinterpret_cast<const float2*>(z + (size_t)s0 * 64 + lane * 2));
        float2 v1 = __ldg(reinterpret_cast<const float2*>(z + (size_t)s1 * 64 + lane * 2));
        acc.x += v0.x + v1.x; acc.y += v0.y + v1.y;
    }
    if (j < len) {
        int s0 = __ldg(adj + st + j);
        float2 v0 = __ldg(reinterpret_cast<const float2*>(z + (size_t)s0 * 64 + lane * 2));
        acc.x += v0.x; acc.y += v0.y;
    }
    float c = __ldg(rsin + w);
    float2* hp = reinterpret_cast<float2*>(out + (size_t)w * 64 + lane * 2);
    float2 cur = *hp;
    cur.x += c * acc.x; cur.y += c * acc.y;
    *hp = cur;
}

// ---------------- elementwise epilogues --------------------------------------
__global__ void relu_bias128(float* __restrict__ h, const float* __restrict__ b1, int n) {
    int i = blockIdx.x * blockDim.x + threadIdx.x;
    if (i >= n) return;
    int c = i & 127;
    float b = __ldg(b1 + c) + __ldg(b1 + 128 + c) + __ldg(b1 + 256 + c);
    float v = h[i] + b;
    h[i] = v > 0.f ? v : 0.f;
}

__global__ void bias64(float* __restrict__ o, const float* __restrict__ b2, int n) {
    int i = blockIdx.x * blockDim.x + threadIdx.x;
    if (i >= n) return;
    int c = i & 63;
    o[i] += __ldg(b2 + c) + __ldg(b2 + 64 + c) + __ldg(b2 + 128 + c);
}

// ---------------- orchestration ----------------------------------------------
extern "C" void kernel_launch(void* const* d_in, const int* in_sizes, int n_in,
                              void* d_out, int out_size) {
    const float* x  = (const float*)d_in[0];
    const float* W1 = (const float*)d_in[1];
    const float* b1 = (const float*)d_in[2];
    const float* W2 = (const float*)d_in[3];
    const float* b2 = (const float*)d_in[4];
    const int*   ei = (const int*)d_in[5];
    float* out = (float*)d_out;

    const int M = in_sizes[0] / DIN;
    const int E = in_sizes[5] / (2 * NREL * 2);

    float *z, *h, *degf;
    int *degi, *off, *cnt, *adj, *bsum;
    cudaGetSymbolAddress((void**)&z,    g_z);
    cudaGetSymbolAddress((void**)&h,    g_h);
    cudaGetSymbolAddress((void**)&degf, g_degf);
    cudaGetSymbolAddress((void**)&degi, g_degi);
    cudaGetSymbolAddress((void**)&off,  g_off);
    cudaGetSymbolAddress((void**)&cnt,  g_cnt);
    cudaGetSymbolAddress((void**)&adj,  g_adj);
    cudaGetSymbolAddress((void**)&bsum, g_bsum);

    const int TB = 256;
    auto blocks = [](long n, int tb) { return (int)((n + tb - 1) / tb); };
    const int nblk_scan = (M + SCAN_CHUNK - 1) / SCAN_CHUNK;

    // --- zero counters / accumulators (memset nodes are graph-capturable) ----
    cudaMemsetAsync(degi, 0, (size_t)12 * M * sizeof(int));
    cudaMemsetAsync(cnt,  0, (size_t)NPAIR * M * sizeof(int));
    cudaMemsetAsync(h,    0, (size_t)M * DH * sizeof(float));
    cudaMemsetAsync(out,  0, (size_t)M * DOUT * sizeof(float));

    // --- degrees + CSR build for all 6 pairs ----------------------------------
    { dim3 g(blocks(E, TB), NPAIR); count_deg_kernel<<<g, TB>>>(ei, degi, E, M); }
    rsqrt_kernel<<<blocks((long)12 * M, TB), TB>>>(degi, degf, 12 * M);
    { dim3 g(nblk_scan, NPAIR); scanA<<<g, 256>>>(degi, off, bsum, M); }
    scanB<<<NPAIR, MAXBLK>>>(bsum, nblk_scan);
    { dim3 g(blocks(M, TB), NPAIR); scanC<<<g, TB>>>(off, bsum, M); }
    { dim3 g(blocks(E, TB), NPAIR); fill_adj_kernel<<<g, TB>>>(ei, off, cnt, adj, E, M); }

    const int gemm_grid = (M + 127) / 128;
    const int gw = blocks((long)M * 32, TB);      // gather grids (warp per node)

    // --- layer 1 ---------------------------------------------------------------
    for (int r = 0; r < NREL; r++) {
        int p = 0 * NREL + r;
        gemm_rowscale<128, 8><<<gemm_grid, 256>>>(
            x, W1 + (size_t)r * DIN * DH, degf + (size_t)(p * 2 + 0) * M, z, M);
        gather128<<<gw, TB>>>(z, h,
            off + (size_t)p * M, degi + (size_t)(p * 2 + 1) * M,
            adj + (size_t)p * E, degf + (size_t)(p * 2 + 1) * M, M);
    }
    relu_bias128<<<blocks((long)M * DH, TB), TB>>>(h, b1, M * DH);

    // --- layer 2 ---------------------------------------------------------------
    for (int r = 0; r < NREL; r++) {
        int p = 1 * NREL + r;
        gemm_rowscale<64, 4><<<gemm_grid, 256>>>(
            h, W2 + (size_t)r * DH * DOUT, degf + (size_t)(p * 2 + 0) * M, z, M);
        gather64<<<gw, TB>>>(z, out,
            off + (size_t)p * M, degi + (size_t)(p * 2 + 1) * M,
            adj + (size_t)p * E, degf + (size_t)(p * 2 + 1) * M, M);
    }
    bias64<<<blocks((long)M * DOUT, TB), TB>>>(out, b2, M * DOUT);
}

// round 10
// speedup vs baseline: 1.0823x; 1.0823x over previous
#include <cuda_runtime.h>
#include <cuda_bf16.h>
#include <mma.h>
#include <cstdint>

using namespace nvcuda;

// ---------------- problem constants ------------------------------------------
#define NMAX   100000
#define EMAX   1600000
#define DIN    128
#define DH     128
#define DOUT   64
#define NREL   3
#define NPAIR  6
#define SCAN_CHUNK 1024
#define MAXBLK 128

// ---------------- scratch (__device__ globals; no allocation allowed) --------
__device__ float g_z[(size_t)NMAX * DIN];            // per-relation z (fp32)
__device__ float g_h[(size_t)NMAX * DH];             // layer-1 accumulator
__device__ __nv_bfloat16 g_ahi[(size_t)NMAX * DIN];  // split of x / h
__device__ __nv_bfloat16 g_alo[(size_t)NMAX * DIN];
__device__ __nv_bfloat16 g_w1hi[NREL * DIN * DH], g_w1lo[NREL * DIN * DH];
__device__ __nv_bfloat16 g_w2hi[NREL * DH * DOUT], g_w2lo[NREL * DH * DOUT];
__device__ int   g_degi[12 * NMAX];
__device__ float g_degf[12 * NMAX];
__device__ int   g_off [NPAIR * NMAX];
__device__ int   g_cnt [NPAIR * NMAX];
__device__ int   g_adj [(size_t)NPAIR * EMAX];
__device__ int   g_bsum[NPAIR * MAXBLK];

// ---------------- fp32 -> (bf16 hi, bf16 lo) split ---------------------------
__global__ void split_kernel(const float* __restrict__ src,
                             __nv_bfloat16* __restrict__ hi,
                             __nv_bfloat16* __restrict__ lo, int n) {
    int i = blockIdx.x * blockDim.x + threadIdx.x;
    if (i >= n) return;
    float v = __ldg(src + i);
    __nv_bfloat16 h = __float2bfloat16(v);
    hi[i] = h;
    lo[i] = __float2bfloat16(v - __bfloat162float(h));
}

// ---------------- degree counting --------------------------------------------
__global__ void count_deg_kernel(const int* __restrict__ ei, int* __restrict__ degi,
                                 int E, int M) {
    int p = blockIdx.y;
    int e = blockIdx.x * blockDim.x + threadIdx.x;
    if (e >= E) return;
    int s = __ldg(ei + (size_t)(p * 2 + 0) * E + e);
    int d = __ldg(ei + (size_t)(p * 2 + 1) * E + e);
    atomicAdd(degi + (size_t)(p * 2 + 0) * M + s, 1);
    atomicAdd(degi + (size_t)(p * 2 + 1) * M + d, 1);
}

__global__ void rsqrt_kernel(const int* __restrict__ degi, float* __restrict__ degf, int n) {
    int i = blockIdx.x * blockDim.x + threadIdx.x;
    if (i < n) degf[i] = rsqrtf((float)max(degi[i], 1));
}

// ---------------- exclusive scan -> CSR offsets -------------------------------
__global__ __launch_bounds__(256)
void scanA(const int* __restrict__ degi, int* __restrict__ off,
           int* __restrict__ bsum, int M) {
    int p = blockIdx.y;
    const int* deg = degi + (size_t)(p * 2 + 1) * M;
    int* o = off + (size_t)p * M;
    int base = blockIdx.x * SCAN_CHUNK;
    int tid = threadIdx.x;

    int v[4];
    int t = 0;
    #pragma unroll
    for (int k = 0; k < 4; k++) {
        int idx = base + tid * 4 + k;
        v[k] = (idx < M) ? deg[idx] : 0;
        t += v[k];
    }
    __shared__ int sm[256];
    sm[tid] = t;
    __syncthreads();
    #pragma unroll
    for (int ofs = 1; ofs < 256; ofs <<= 1) {
        int u = (tid >= ofs) ? sm[tid - ofs] : 0;
        __syncthreads();
        sm[tid] += u;
        __syncthreads();
    }
    int run = sm[tid] - t;
    #pragma unroll
    for (int k = 0; k < 4; k++) {
        int idx = base + tid * 4 + k;
        if (idx < M) o[idx] = run;
        run += v[k];
    }
    if (tid == 255) bsum[p * MAXBLK + blockIdx.x] = sm[255];
}

__global__ __launch_bounds__(MAXBLK)
void scanB(int* __restrict__ bsum, int nblk) {
    int p = blockIdx.x;
    int tid = threadIdx.x;
    int* b = bsum + p * MAXBLK;
    int t = (tid < nblk) ? b[tid] : 0;
    __shared__ int sm[MAXBLK];
    sm[tid] = t;
    __syncthreads();
    #pragma unroll
    for (int ofs = 1; ofs < MAXBLK; ofs <<= 1) {
        int u = (tid >= ofs) ? sm[tid - ofs] : 0;
        __syncthreads();
        sm[tid] += u;
        __syncthreads();
    }
    if (tid < nblk) b[tid] = sm[tid] - t;
}

__global__ void scanC(int* __restrict__ off, const int* __restrict__ bsum, int M) {
    int p = blockIdx.y;
    int i = blockIdx.x * blockDim.x + threadIdx.x;
    if (i < M) off[(size_t)p * M + i] += bsum[p * MAXBLK + (i >> 10)];
}

__global__ void fill_adj_kernel(const int* __restrict__ ei, const int* __restrict__ off,
                                int* __restrict__ cnt, int* __restrict__ adj,
                                int E, int M) {
    int p = blockIdx.y;
    int e = blockIdx.x * blockDim.x + threadIdx.x;
    if (e >= E) return;
    int s = __ldg(ei + (size_t)(p * 2 + 0) * E + e);
    int d = __ldg(ei + (size_t)(p * 2 + 1) * E + e);
    int pos = atomicAdd(cnt + (size_t)p * M + d, 1);
    adj[(size_t)p * E + off[(size_t)p * M + d] + pos] = s;
}

// ---------------- bf16-split tensor-core GEMM --------------------------------
// C[M,BN] = rs[row] * (A @ B), A fp32 split into (Ahi,Alo)[M,128] bf16,
// B split into (Bhi,Blo)[128,BN] bf16.  hi*hi + hi*lo + lo*hi products.
// BM=128, 256 threads = 8 warps; warp grid WROWS x (8/WROWS), warp tile
// (128/WROWS) x 64 -> MT x 4 wmma 16x16x16 tiles per warp.
#define A_STRIDE 40     // 32 + 8 pad (bf16 elems): 80B rows, conflict-free ldsm
#define B_STRIDE 136    // BNmax + 8 pad: 272B rows
#define EPI_STRIDE 68   // 64 + 4 pad (fp32)

template<int BN, int WROWS>
__global__ __launch_bounds__(256)
void gemm_bf16split(const __nv_bfloat16* __restrict__ Ahi,
                    const __nv_bfloat16* __restrict__ Alo,
                    const __nv_bfloat16* __restrict__ Bhi,
                    const __nv_bfloat16* __restrict__ Blo,
                    const float* __restrict__ rs,
                    float* __restrict__ C, int M) {
    constexpr int BM = 128;
    constexpr int BK = 32;
    constexpr int MT = BM / WROWS / 16;      // wmma m-tiles per warp

    __shared__ __align__(16) char smem[38912];
    __nv_bfloat16* sAhi = reinterpret_cast<__nv_bfloat16*>(smem);              // 10240 B
    __nv_bfloat16* sAlo = sAhi + BM * A_STRIDE;                                 // 10240 B
    __nv_bfloat16* sBhi = reinterpret_cast<__nv_bfloat16*>(smem + 20480);      //  8704 B
    __nv_bfloat16* sBlo = sBhi + BK * B_STRIDE;                                 //  8704 B

    const int tid  = threadIdx.x;
    const int w    = tid >> 5;
    const int lane = tid & 31;
    const int warp_row = w % WROWS;
    const int warp_col = w / WROWS;
    const int m_off = warp_row * (BM / WROWS);
    const int n_off = warp_col * 64;
    const int row0 = blockIdx.x * BM;

    wmma::fragment<wmma::accumulator, 16, 16, 16, float> acc[MT][4];
    #pragma unroll
    for (int mt = 0; mt < MT; mt++)
        #pragma unroll
        for (int n = 0; n < 4; n++) wmma::fill_fragment(acc[mt][n], 0.0f);

    for (int kc = 0; kc < 128; kc += BK) {
        if (kc) __syncthreads();
        // A chunk: 128 x 32 bf16 -> 512 uint4 slots (hi and lo)
        #pragma unroll
        for (int i = 0; i < 2; i++) {
            int slot = tid + i * 256;
            int r  = slot >> 2;
            int c8 = (slot & 3) * 8;
            int gr = row0 + r;
            uint4 vh = make_uint4(0, 0, 0, 0), vl = make_uint4(0, 0, 0, 0);
            if (gr < M) {
                vh = *reinterpret_cast<const uint4*>(Ahi + (size_t)gr * 128 + kc + c8);
                vl = *reinterpret_cast<const uint4*>(Alo + (size_t)gr * 128 + kc + c8);
            }
            *reinterpret_cast<uint4*>(sAhi + r * A_STRIDE + c8) = vh;
            *reinterpret_cast<uint4*>(sAlo + r * A_STRIDE + c8) = vl;
        }
        // B chunk: 32 x BN bf16
        constexpr int BSLOT = BK * BN / 8;
        #pragma unroll
        for (int i = 0; i < BSLOT / 256; i++) {
            int slot = tid + i * 256;
            int r  = slot / (BN / 8);
            int c8 = (slot % (BN / 8)) * 8;
            *reinterpret_cast<uint4*>(sBhi + r * B_STRIDE + c8) =
                *reinterpret_cast<const uint4*>(Bhi + (size_t)(kc + r) * BN + c8);
            *reinterpret_cast<uint4*>(sBlo + r * B_STRIDE + c8) =
                *reinterpret_cast<const uint4*>(Blo + (size_t)(kc + r) * BN + c8);
        }
        __syncthreads();

        #pragma unroll
        for (int ks = 0; ks < BK; ks += 16) {
            wmma::fragment<wmma::matrix_a, 16, 16, 16, __nv_bfloat16, wmma::row_major> ahi[MT], alo[MT];
            wmma::fragment<wmma::matrix_b, 16, 16, 16, __nv_bfloat16, wmma::row_major> bhi[4], blo[4];
            #pragma unroll
            for (int mt = 0; mt < MT; mt++) {
                wmma::load_matrix_sync(ahi[mt], sAhi + (m_off + mt * 16) * A_STRIDE + ks, A_STRIDE);
                wmma::load_matrix_sync(alo[mt], sAlo + (m_off + mt * 16) * A_STRIDE + ks, A_STRIDE);
            }
            #pragma unroll
            for (int n = 0; n < 4; n++) {
                wmma::load_matrix_sync(bhi[n], sBhi + ks * B_STRIDE + n_off + n * 16, B_STRIDE);
                wmma::load_matrix_sync(blo[n], sBlo + ks * B_STRIDE + n_off + n * 16, B_STRIDE);
            }
            #pragma unroll
            for (int mt = 0; mt < MT; mt++)
                #pragma unroll
                for (int n = 0; n < 4; n++) {
                    wmma::mma_sync(acc[mt][n], ahi[mt], bhi[n], acc[mt][n]);
                    wmma::mma_sync(acc[mt][n], ahi[mt], blo[n], acc[mt][n]);
                    wmma::mma_sync(acc[mt][n], alo[mt], bhi[n], acc[mt][n]);
                }
        }
    }

    // epilogue: per-warp smem staging (reuses operand smem), scale by rs[row]
    __syncthreads();
    float* epi = reinterpret_cast<float*>(smem + w * 16 * EPI_STRIDE * 4);
    #pragma unroll
    for (int mt = 0; mt < MT; mt++) {
        #pragma unroll
        for (int n = 0; n < 4; n++)
            wmma::store_matrix_sync(epi + n * 16, acc[mt][n], EPI_STRIDE, wmma::mem_row_major);
        __syncwarp();
        int gr0 = row0 + m_off + mt * 16;
        #pragma unroll
        for (int it = 0; it < 8; it++) {
            int idx = it * 32 + lane;           // 16 rows x 16 float4
            int r  = idx >> 4;
            int c4 = (idx & 15) * 4;
            int gr = gr0 + r;
            if (gr < M) {
                float s = __ldg(rs + gr);
                float4 v = *reinterpret_cast<float4*>(epi + r * EPI_STRIDE + c4);
                v.x *= s; v.y *= s; v.z *= s; v.w *= s;
                *reinterpret_cast<float4*>(C + (size_t)gr * BN + n_off + c4) = v;
            }
        }
        __syncwarp();
    }
}

// ---------------- CSR gather aggregation --------------------------------------
__global__ __launch_bounds__(256)
void gather128(const float* __restrict__ z, float* __restrict__ out,
               const int* __restrict__ off, const int* __restrict__ degin,
               const int* __restrict__ adj, const float* __restrict__ rsin, int M) {
    int w = (blockIdx.x * blockDim.x + threadIdx.x) >> 5;
    if (w >= M) return;
    int lane = threadIdx.x & 31;
    int st = __ldg(off + w);
    int len = __ldg(degin + w);
    float4 acc = make_float4(0.f, 0.f, 0.f, 0.f);
    int j = 0;
    for (; j + 1 < len; j += 2) {
        int s0 = __ldg(adj + st + j);
        int s1 = __ldg(adj + st + j + 1);
        float4 v0 = __ldg(reinterpret_cast<const float4*>(z + (size_t)s0 * 128 + lane * 4));
        float4 v1 = __ldg(reinterpret_cast<const float4*>(z + (size_t)s1 * 128 + lane * 4));
        acc.x += v0.x + v1.x; acc.y += v0.y + v1.y;
        acc.z += v0.z + v1.z; acc.w += v0.w + v1.w;
    }
    if (j < len) {
        int s0 = __ldg(adj + st + j);
        float4 v0 = __ldg(reinterpret_cast<const float4*>(z + (size_t)s0 * 128 + lane * 4));
        acc.x += v0.x; acc.y += v0.y; acc.z += v0.z; acc.w += v0.w;
    }
    float c = __ldg(rsin + w);
    float4* hp = reinterpret_cast<float4*>(out + (size_t)w * 128 + lane * 4);
    float4 cur = *hp;
    cur.x += c * acc.x; cur.y += c * acc.y;
    cur.z += c * acc.z; cur.w += c * acc.w;
    *hp = cur;
}

__global__ __launch_bounds__(256)
void gather64(const float* __restrict__ z, float* __restrict__ out,
              const int* __restrict__ off, const int* __restrict__ degin,
              const int* __restrict__ adj, const float* __restrict__ rsin, int M) {
    int w = (blockIdx.x * blockDim.x + threadIdx.x) >> 5;
    if (w >= M) return;
    int lane = threadIdx.x & 31;
    int st = __ldg(off + w);
    int len = __ldg(degin + w);
    float2 acc = make_float2(0.f, 0.f);
    int j = 0;
    for (; j + 1 < len; j += 2) {
        int s0 = __ldg(adj + st + j);
        int s1 = __ldg(adj + st + j + 1);
        float2 v0 = __ldg(reinterpret_cast<const float2*>(z + (size_t)s0 * 64 + lane * 2));
        float2 v1 = __ldg(reinterpret_cast<const float2*>(z + (size_t)s1 * 64 + lane * 2));
        acc.x += v0.x + v1.x; acc.y += v0.y + v1.y;
    }
    if (j < len) {
        int s0 = __ldg(adj + st + j);
        float2 v0 = __ldg(reinterpret_cast<const float2*>(z + (size_t)s0 * 64 + lane * 2));
        acc.x += v0.x; acc.y += v0.y;
    }
    float c = __ldg(rsin + w);
    float2* hp = reinterpret_cast<float2*>(out + (size_t)w * 64 + lane * 2);
    float2 cur = *hp;
    cur.x += c * acc.x; cur.y += c * acc.y;
    *hp = cur;
}

// ---------------- elementwise epilogues --------------------------------------
__global__ void relu_bias128(float* __restrict__ h, const float* __restrict__ b1, int n) {
    int i = blockIdx.x * blockDim.x + threadIdx.x;
    if (i >= n) return;
    int c = i & 127;
    float b = __ldg(b1 + c) + __ldg(b1 + 128 + c) + __ldg(b1 + 256 + c);
    float v = h[i] + b;
    h[i] = v > 0.f ? v : 0.f;
}

__global__ void bias64(float* __restrict__ o, const float* __restrict__ b2, int n) {
    int i = blockIdx.x * blockDim.x + threadIdx.x;
    if (i >= n) return;
    int c = i & 63;
    o[i] += __ldg(b2 + c) + __ldg(b2 + 64 + c) + __ldg(b2 + 128 + c);
}

// ---------------- orchestration ----------------------------------------------
extern "C" void kernel_launch(void* const* d_in, const int* in_sizes, int n_in,
                              void* d_out, int out_size) {
    const float* x  = (const float*)d_in[0];
    const float* W1 = (const float*)d_in[1];
    const float* b1 = (const float*)d_in[2];
    const float* W2 = (const float*)d_in[3];
    const float* b2 = (const float*)d_in[4];
    const int*   ei = (const int*)d_in[5];
    float* out = (float*)d_out;

    const int M = in_sizes[0] / DIN;
    const int E = in_sizes[5] / (2 * NREL * 2);

    float *z, *h, *degf;
    __nv_bfloat16 *ahi, *alo, *w1hi, *w1lo, *w2hi, *w2lo;
    int *degi, *off, *cnt, *adj, *bsum;
    cudaGetSymbolAddress((void**)&z,    g_z);
    cudaGetSymbolAddress((void**)&h,    g_h);
    cudaGetSymbolAddress((void**)&ahi,  g_ahi);
    cudaGetSymbolAddress((void**)&alo,  g_alo);
    cudaGetSymbolAddress((void**)&w1hi, g_w1hi);
    cudaGetSymbolAddress((void**)&w1lo, g_w1lo);
    cudaGetSymbolAddress((void**)&w2hi, g_w2hi);
    cudaGetSymbolAddress((void**)&w2lo, g_w2lo);
    cudaGetSymbolAddress((void**)&degf, g_degf);
    cudaGetSymbolAddress((void**)&degi, g_degi);
    cudaGetSymbolAddress((void**)&off,  g_off);
    cudaGetSymbolAddress((void**)&cnt,  g_cnt);
    cudaGetSymbolAddress((void**)&adj,  g_adj);
    cudaGetSymbolAddress((void**)&bsum, g_bsum);

    const int TB = 256;
    auto blocks = [](long n, int tb) { return (int)((n + tb - 1) / tb); };
    const int nblk_scan = (M + SCAN_CHUNK - 1) / SCAN_CHUNK;

    cudaMemsetAsync(degi, 0, (size_t)12 * M * sizeof(int));
    cudaMemsetAsync(cnt,  0, (size_t)NPAIR * M * sizeof(int));
    cudaMemsetAsync(h,    0, (size_t)M * DH * sizeof(float));
    cudaMemsetAsync(out,  0, (size_t)M * DOUT * sizeof(float));

    // --- degrees + CSR ---------------------------------------------------------
    { dim3 g(blocks(E, TB), NPAIR); count_deg_kernel<<<g, TB>>>(ei, degi, E, M); }
    rsqrt_kernel<<<blocks((long)12 * M, TB), TB>>>(degi, degf, 12 * M);
    { dim3 g(nblk_scan, NPAIR); scanA<<<g, 256>>>(degi, off, bsum, M); }
    scanB<<<NPAIR, MAXBLK>>>(bsum, nblk_scan);
    { dim3 g(blocks(M, TB), NPAIR); scanC<<<g, TB>>>(off, bsum, M); }
    { dim3 g(blocks(E, TB), NPAIR); fill_adj_kernel<<<g, TB>>>(ei, off, cnt, adj, E, M); }

    // --- operand splits --------------------------------------------------------
    split_kernel<<<blocks((long)M * DIN, TB), TB>>>(x, ahi, alo, M * DIN);
    split_kernel<<<blocks(NREL * DIN * DH, TB), TB>>>(W1, w1hi, w1lo, NREL * DIN * DH);
    split_kernel<<<blocks(NREL * DH * DOUT, TB), TB>>>(W2, w2hi, w2lo, NREL * DH * DOUT);

    const int gemm_grid = (M + 127) / 128;
    const int gw = blocks((long)M * 32, TB);

    // --- layer 1 ----------------------------------------------------------------
    for (int r = 0; r < NREL; r++) {
        int p = 0 * NREL + r;
        gemm_bf16split<128, 4><<<gemm_grid, 256>>>(
            ahi, alo, w1hi + (size_t)r * DIN * DH, w1lo + (size_t)r * DIN * DH,
            degf + (size_t)(p * 2 + 0) * M, z, M);
        gather128<<<gw, TB>>>(z, h,
            off + (size_t)p * M, degi + (size_t)(p * 2 + 1) * M,
            adj + (size_t)p * E, degf + (size_t)(p * 2 + 1) * M, M);
    }
    relu_bias128<<<blocks((long)M * DH, TB), TB>>>(h, b1, M * DH);

    // --- layer 2 ----------------------------------------------------------------
    split_kernel<<<blocks((long)M * DH, TB), TB>>>(h, ahi, alo, M * DH);
    for (int r = 0; r < NREL; r++) {
        int p = 1 * NREL + r;
        gemm_bf16split<64, 8><<<gemm_grid, 256>>>(
            ahi, alo, w2hi + (size_t)r * DH * DOUT, w2lo + (size_t)r * DH * DOUT,
            degf + (size_t)(p * 2 + 0) * M, z, M);
        gather64<<<gw, TB>>>(z, out,
            off + (size_t)p * M, degi + (size_t)(p * 2 + 1) * M,
            adj + (size_t)p * E, degf + (size_t)(p * 2 + 1) * M, M);
    }
    bias64<<<blocks((long)M * DOUT, TB), TB>>>(out, b2, M * DOUT);
}

// round 11
// speedup vs baseline: 1.2491x; 1.1542x over previous
#include <cuda_runtime.h>
#include <cuda_bf16.h>
#include <cuda_fp16.h>
#include <mma.h>
#include <cstdint>

using namespace nvcuda;

// ---------------- problem constants ------------------------------------------
#define NMAX   100000
#define EMAX   1600000
#define DIN    128
#define DH     128
#define DOUT   64
#define NREL   3
#define NPAIR  6
#define SCAN_CHUNK 1024
#define MAXBLK 128

// ---------------- scratch (__device__ globals; no allocation allowed) --------
__device__ __half g_zh[(size_t)NMAX * DIN];          // per-relation z (fp16)
__device__ float g_h[(size_t)NMAX * DH];             // layer-1 accumulator (fp32)
__device__ __nv_bfloat16 g_ahi[(size_t)NMAX * DIN];  // split of x / h
__device__ __nv_bfloat16 g_alo[(size_t)NMAX * DIN];
__device__ __nv_bfloat16 g_w1hi[NREL * DIN * DH], g_w1lo[NREL * DIN * DH];
__device__ __nv_bfloat16 g_w2hi[NREL * DH * DOUT], g_w2lo[NREL * DH * DOUT];
__device__ int   g_degi[12 * NMAX];
__device__ float g_degf[12 * NMAX];
__device__ int   g_off [NPAIR * NMAX];
__device__ int   g_cnt [NPAIR * NMAX];               // fill cursors (= off after scanC)
__device__ int   g_adj [(size_t)NPAIR * EMAX];
__device__ int   g_bsum[NPAIR * MAXBLK];

// ---------------- fp32 -> (bf16 hi, bf16 lo) split ---------------------------
__global__ void split_kernel(const float* __restrict__ src,
                             __nv_bfloat16* __restrict__ hi,
                             __nv_bfloat16* __restrict__ lo, int n) {
    int i = blockIdx.x * blockDim.x + threadIdx.x;
    if (i >= n) return;
    float v = __ldg(src + i);
    __nv_bfloat16 h = __float2bfloat16(v);
    hi[i] = h;
    lo[i] = __float2bfloat16(v - __bfloat162float(h));
}

// ---------------- degree counting --------------------------------------------
__global__ void count_deg_kernel(const int* __restrict__ ei, int* __restrict__ degi,
                                 int E, int M) {
    int p = blockIdx.y;
    int e = blockIdx.x * blockDim.x + threadIdx.x;
    if (e >= E) return;
    int s = __ldg(ei + (size_t)(p * 2 + 0) * E + e);
    int d = __ldg(ei + (size_t)(p * 2 + 1) * E + e);
    atomicAdd(degi + (size_t)(p * 2 + 0) * M + s, 1);
    atomicAdd(degi + (size_t)(p * 2 + 1) * M + d, 1);
}

__global__ void rsqrt_kernel(const int* __restrict__ degi, float* __restrict__ degf, int n) {
    int i = blockIdx.x * blockDim.x + threadIdx.x;
    if (i < n) degf[i] = rsqrtf((float)max(degi[i], 1));
}

// ---------------- exclusive scan -> CSR offsets -------------------------------
__global__ __launch_bounds__(256)
void scanA(const int* __restrict__ degi, int* __restrict__ off,
           int* __restrict__ bsum, int M) {
    int p = blockIdx.y;
    const int* deg = degi + (size_t)(p * 2 + 1) * M;
    int* o = off + (size_t)p * M;
    int base = blockIdx.x * SCAN_CHUNK;
    int tid = threadIdx.x;

    int v[4];
    int t = 0;
    #pragma unroll
    for (int k = 0; k < 4; k++) {
        int idx = base + tid * 4 + k;
        v[k] = (idx < M) ? deg[idx] : 0;
        t += v[k];
    }
    __shared__ int sm[256];
    sm[tid] = t;
    __syncthreads();
    #pragma unroll
    for (int ofs = 1; ofs < 256; ofs <<= 1) {
        int u = (tid >= ofs) ? sm[tid - ofs] : 0;
        __syncthreads();
        sm[tid] += u;
        __syncthreads();
    }
    int run = sm[tid] - t;
    #pragma unroll
    for (int k = 0; k < 4; k++) {
        int idx = base + tid * 4 + k;
        if (idx < M) o[idx] = run;
        run += v[k];
    }
    if (tid == 255) bsum[p * MAXBLK + blockIdx.x] = sm[255];
}

__global__ __launch_bounds__(MAXBLK)
void scanB(int* __restrict__ bsum, int nblk) {
    int p = blockIdx.x;
    int tid = threadIdx.x;
    int* b = bsum + p * MAXBLK;
    int t = (tid < nblk) ? b[tid] : 0;
    __shared__ int sm[MAXBLK];
    sm[tid] = t;
    __syncthreads();
    #pragma unroll
    for (int ofs = 1; ofs < MAXBLK; ofs <<= 1) {
        int u = (tid >= ofs) ? sm[tid - ofs] : 0;
        __syncthreads();
        sm[tid] += u;
        __syncthreads();
    }
    if (tid < nblk) b[tid] = sm[tid] - t;
}

// Phase C: add block bases; also initialize fill cursors (cnt = off).
__global__ void scanC(int* __restrict__ off, int* __restrict__ cnt,
                      const int* __restrict__ bsum, int M) {
    int p = blockIdx.y;
    int i = blockIdx.x * blockDim.x + threadIdx.x;
    if (i < M) {
        int v = off[(size_t)p * M + i] + bsum[p * MAXBLK + (i >> 10)];
        off[(size_t)p * M + i] = v;
        cnt[(size_t)p * M + i] = v;
    }
}

// ---------------- CSR fill: cursor atomics give global slot directly ---------
__global__ void fill_adj_kernel(const int* __restrict__ ei,
                                int* __restrict__ cnt, int* __restrict__ adj,
                                int E, int M) {
    int p = blockIdx.y;
    int e = blockIdx.x * blockDim.x + threadIdx.x;
    if (e >= E) return;
    int s = __ldg(ei + (size_t)(p * 2 + 0) * E + e);
    int d = __ldg(ei + (size_t)(p * 2 + 1) * E + e);
    int pos = atomicAdd(cnt + (size_t)p * M + d, 1);
    adj[(size_t)p * E + pos] = s;
}

// ---------------- bf16-split tensor-core GEMM, fp16 output -------------------
#define A_STRIDE 40
#define B_STRIDE 136
#define EPI_STRIDE 68

template<int BN, int WROWS>
__global__ __launch_bounds__(256)
void gemm_bf16split(const __nv_bfloat16* __restrict__ Ahi,
                    const __nv_bfloat16* __restrict__ Alo,
                    const __nv_bfloat16* __restrict__ Bhi,
                    const __nv_bfloat16* __restrict__ Blo,
                    const float* __restrict__ rs,
                    __half* __restrict__ C, int M) {
    constexpr int BM = 128;
    constexpr int BK = 32;
    constexpr int MT = BM / WROWS / 16;

    __shared__ __align__(16) char smem[38912];
    __nv_bfloat16* sAhi = reinterpret_cast<__nv_bfloat16*>(smem);
    __nv_bfloat16* sAlo = sAhi + BM * A_STRIDE;
    __nv_bfloat16* sBhi = reinterpret_cast<__nv_bfloat16*>(smem + 20480);
    __nv_bfloat16* sBlo = sBhi + BK * B_STRIDE;

    const int tid  = threadIdx.x;
    const int w    = tid >> 5;
    const int lane = tid & 31;
    const int warp_row = w % WROWS;
    const int warp_col = w / WROWS;
    const int m_off = warp_row * (BM / WROWS);
    const int n_off = warp_col * 64;
    const int row0 = blockIdx.x * BM;

    wmma::fragment<wmma::accumulator, 16, 16, 16, float> acc[MT][4];
    #pragma unroll
    for (int mt = 0; mt < MT; mt++)
        #pragma unroll
        for (int n = 0; n < 4; n++) wmma::fill_fragment(acc[mt][n], 0.0f);

    for (int kc = 0; kc < 128; kc += BK) {
        if (kc) __syncthreads();
        #pragma unroll
        for (int i = 0; i < 2; i++) {
            int slot = tid + i * 256;
            int r  = slot >> 2;
            int c8 = (slot & 3) * 8;
            int gr = row0 + r;
            uint4 vh = make_uint4(0, 0, 0, 0), vl = make_uint4(0, 0, 0, 0);
            if (gr < M) {
                vh = *reinterpret_cast<const uint4*>(Ahi + (size_t)gr * 128 + kc + c8);
                vl = *reinterpret_cast<const uint4*>(Alo + (size_t)gr * 128 + kc + c8);
            }
            *reinterpret_cast<uint4*>(sAhi + r * A_STRIDE + c8) = vh;
            *reinterpret_cast<uint4*>(sAlo + r * A_STRIDE + c8) = vl;
        }
        constexpr int BSLOT = BK * BN / 8;
        #pragma unroll
        for (int i = 0; i < BSLOT / 256; i++) {
            int slot = tid + i * 256;
            int r  = slot / (BN / 8);
            int c8 = (slot % (BN / 8)) * 8;
            *reinterpret_cast<uint4*>(sBhi + r * B_STRIDE + c8) =
                *reinterpret_cast<const uint4*>(Bhi + (size_t)(kc + r) * BN + c8);
            *reinterpret_cast<uint4*>(sBlo + r * B_STRIDE + c8) =
                *reinterpret_cast<const uint4*>(Blo + (size_t)(kc + r) * BN + c8);
        }
        __syncthreads();

        #pragma unroll
        for (int ks = 0; ks < BK; ks += 16) {
            wmma::fragment<wmma::matrix_a, 16, 16, 16, __nv_bfloat16, wmma::row_major> ahi[MT], alo[MT];
            wmma::fragment<wmma::matrix_b, 16, 16, 16, __nv_bfloat16, wmma::row_major> bhi[4], blo[4];
            #pragma unroll
            for (int mt = 0; mt < MT; mt++) {
                wmma::load_matrix_sync(ahi[mt], sAhi + (m_off + mt * 16) * A_STRIDE + ks, A_STRIDE);
                wmma::load_matrix_sync(alo[mt], sAlo + (m_off + mt * 16) * A_STRIDE + ks, A_STRIDE);
            }
            #pragma unroll
            for (int n = 0; n < 4; n++) {
                wmma::load_matrix_sync(bhi[n], sBhi + ks * B_STRIDE + n_off + n * 16, B_STRIDE);
                wmma::load_matrix_sync(blo[n], sBlo + ks * B_STRIDE + n_off + n * 16, B_STRIDE);
            }
            #pragma unroll
            for (int mt = 0; mt < MT; mt++)
                #pragma unroll
                for (int n = 0; n < 4; n++) {
                    wmma::mma_sync(acc[mt][n], ahi[mt], bhi[n], acc[mt][n]);
                    wmma::mma_sync(acc[mt][n], ahi[mt], blo[n], acc[mt][n]);
                    wmma::mma_sync(acc[mt][n], alo[mt], bhi[n], acc[mt][n]);
                }
        }
    }

    // epilogue: scale by rs[row], convert to fp16
    __syncthreads();
    float* epi = reinterpret_cast<float*>(smem + w * 16 * EPI_STRIDE * 4);
    #pragma unroll
    for (int mt = 0; mt < MT; mt++) {
        #pragma unroll
        for (int n = 0; n < 4; n++)
            wmma::store_matrix_sync(epi + n * 16, acc[mt][n], EPI_STRIDE, wmma::mem_row_major);
        __syncwarp();
        int gr0 = row0 + m_off + mt * 16;
        #pragma unroll
        for (int it = 0; it < 8; it++) {
            int idx = it * 32 + lane;
            int r  = idx >> 4;
            int c4 = (idx & 15) * 4;
            int gr = gr0 + r;
            if (gr < M) {
                float s = __ldg(rs + gr);
                float4 v = *reinterpret_cast<float4*>(epi + r * EPI_STRIDE + c4);
                __half2 p0 = __floats2half2_rn(v.x * s, v.y * s);
                __half2 p1 = __floats2half2_rn(v.z * s, v.w * s);
                uint2 o;
                o.x = *reinterpret_cast<uint32_t*>(&p0);
                o.y = *reinterpret_cast<uint32_t*>(&p1);
                *reinterpret_cast<uint2*>(C + (size_t)gr * BN + n_off + c4) = o;
            }
        }
        __syncwarp();
    }
}

// ---------------- CSR gather aggregation (fp16 z, fp32 accum) ----------------
// MODE 0: out = c*acc   MODE 1: out += c*acc
// MODE 2: out = prev + c*acc + sum_bias (RELU optionally)
template<int MODE, bool RELU>
__global__ __launch_bounds__(256)
void gather128h(const __half* __restrict__ z, float* __restrict__ out,
                const int* __restrict__ off, const int* __restrict__ degin,
                const int* __restrict__ adj, const float* __restrict__ rsin,
                const float* __restrict__ bias, int M) {
    int w = (blockIdx.x * blockDim.x + threadIdx.x) >> 5;
    if (w >= M) return;
    int lane = threadIdx.x & 31;
    int st = __ldg(off + w);
    int len = __ldg(degin + w);
    float4 acc = make_float4(0.f, 0.f, 0.f, 0.f);
    int j = 0;
    for (; j + 1 < len; j += 2) {
        int s0 = __ldg(adj + st + j);
        int s1 = __ldg(adj + st + j + 1);
        uint2 r0 = __ldg(reinterpret_cast<const uint2*>(z + (size_t)s0 * 128 + lane * 4));
        uint2 r1 = __ldg(reinterpret_cast<const uint2*>(z + (size_t)s1 * 128 + lane * 4));
        float2 a = __half22float2(*reinterpret_cast<__half2*>(&r0.x));
        float2 b = __half22float2(*reinterpret_cast<__half2*>(&r0.y));
        float2 c2 = __half22float2(*reinterpret_cast<__half2*>(&r1.x));
        float2 d2 = __half22float2(*reinterpret_cast<__half2*>(&r1.y));
        acc.x += a.x + c2.x; acc.y += a.y + c2.y;
        acc.z += b.x + d2.x; acc.w += b.y + d2.y;
    }
    if (j < len) {
        int s0 = __ldg(adj + st + j);
        uint2 r0 = __ldg(reinterpret_cast<const uint2*>(z + (size_t)s0 * 128 + lane * 4));
        float2 a = __half22float2(*reinterpret_cast<__half2*>(&r0.x));
        float2 b = __half22float2(*reinterpret_cast<__half2*>(&r0.y));
        acc.x += a.x; acc.y += a.y; acc.z += b.x; acc.w += b.y;
    }
    float c = __ldg(rsin + w);
    float* hp = out + (size_t)w * 128 + lane * 4;
    float4 r;
    if (MODE == 0) {
        r = make_float4(c * acc.x, c * acc.y, c * acc.z, c * acc.w);
    } else {
        float4 cur = *reinterpret_cast<float4*>(hp);
        r = make_float4(cur.x + c * acc.x, cur.y + c * acc.y,
                        cur.z + c * acc.z, cur.w + c * acc.w);
    }
    if (MODE == 2) {
        int col = lane * 4;
        r.x += __ldg(bias + col + 0) + __ldg(bias + 128 + col + 0) + __ldg(bias + 256 + col + 0);
        r.y += __ldg(bias + col + 1) + __ldg(bias + 128 + col + 1) + __ldg(bias + 256 + col + 1);
        r.z += __ldg(bias + col + 2) + __ldg(bias + 128 + col + 2) + __ldg(bias + 256 + col + 2);
        r.w += __ldg(bias + col + 3) + __ldg(bias + 128 + col + 3) + __ldg(bias + 256 + col + 3);
        if (RELU) {
            r.x = fmaxf(r.x, 0.f); r.y = fmaxf(r.y, 0.f);
            r.z = fmaxf(r.z, 0.f); r.w = fmaxf(r.w, 0.f);
        }
    }
    *reinterpret_cast<float4*>(hp) = r;
}

template<int MODE>
__global__ __launch_bounds__(256)
void gather64h(const __half* __restrict__ z, float* __restrict__ out,
               const int* __restrict__ off, const int* __restrict__ degin,
               const int* __restrict__ adj, const float* __restrict__ rsin,
               const float* __restrict__ bias, int M) {
    int w = (blockIdx.x * blockDim.x + threadIdx.x) >> 5;
    if (w >= M) return;
    int lane = threadIdx.x & 31;
    int st = __ldg(off + w);
    int len = __ldg(degin + w);
    float2 acc = make_float2(0.f, 0.f);
    int j = 0;
    for (; j + 1 < len; j += 2) {
        int s0 = __ldg(adj + st + j);
        int s1 = __ldg(adj + st + j + 1);
        uint32_t r0 = __ldg(reinterpret_cast<const uint32_t*>(z + (size_t)s0 * 64 + lane * 2));
        uint32_t r1 = __ldg(reinterpret_cast<const uint32_t*>(z + (size_t)s1 * 64 + lane * 2));
        float2 a = __half22float2(*reinterpret_cast<__half2*>(&r0));
        float2 b = __half22float2(*reinterpret_cast<__half2*>(&r1));
        acc.x += a.x + b.x; acc.y += a.y + b.y;
    }
    if (j < len) {
        int s0 = __ldg(adj + st + j);
        uint32_t r0 = __ldg(reinterpret_cast<const uint32_t*>(z + (size_t)s0 * 64 + lane * 2));
        float2 a = __half22float2(*reinterpret_cast<__half2*>(&r0));
        acc.x += a.x; acc.y += a.y;
    }
    float c = __ldg(rsin + w);
    float* hp = out + (size_t)w * 64 + lane * 2;
    float2 r;
    if (MODE == 0) {
        r = make_float2(c * acc.x, c * acc.y);
    } else {
        float2 cur = *reinterpret_cast<float2*>(hp);
        r = make_float2(cur.x + c * acc.x, cur.y + c * acc.y);
    }
    if (MODE == 2) {
        int col = lane * 2;
        r.x += __ldg(bias + col + 0) + __ldg(bias + 64 + col + 0) + __ldg(bias + 128 + col + 0);
        r.y += __ldg(bias + col + 1) + __ldg(bias + 64 + col + 1) + __ldg(bias + 128 + col + 1);
    }
    *reinterpret_cast<float2*>(hp) = r;
}

// ---------------- orchestration ----------------------------------------------
extern "C" void kernel_launch(void* const* d_in, const int* in_sizes, int n_in,
                              void* d_out, int out_size) {
    const float* x  = (const float*)d_in[0];
    const float* W1 = (const float*)d_in[1];
    const float* b1 = (const float*)d_in[2];
    const float* W2 = (const float*)d_in[3];
    const float* b2 = (const float*)d_in[4];
    const int*   ei = (const int*)d_in[5];
    float* out = (float*)d_out;

    const int M = in_sizes[0] / DIN;
    const int E = in_sizes[5] / (2 * NREL * 2);

    float *h, *degf;
    __half* zh;
    __nv_bfloat16 *ahi, *alo, *w1hi, *w1lo, *w2hi, *w2lo;
    int *degi, *off, *cnt, *adj, *bsum;
    cudaGetSymbolAddress((void**)&zh,   g_zh);
    cudaGetSymbolAddress((void**)&h,    g_h);
    cudaGetSymbolAddress((void**)&ahi,  g_ahi);
    cudaGetSymbolAddress((void**)&alo,  g_alo);
    cudaGetSymbolAddress((void**)&w1hi, g_w1hi);
    cudaGetSymbolAddress((void**)&w1lo, g_w1lo);
    cudaGetSymbolAddress((void**)&w2hi, g_w2hi);
    cudaGetSymbolAddress((void**)&w2lo, g_w2lo);
    cudaGetSymbolAddress((void**)&degf, g_degf);
    cudaGetSymbolAddress((void**)&degi, g_degi);
    cudaGetSymbolAddress((void**)&off,  g_off);
    cudaGetSymbolAddress((void**)&cnt,  g_cnt);
    cudaGetSymbolAddress((void**)&adj,  g_adj);
    cudaGetSymbolAddress((void**)&bsum, g_bsum);

    const int TB = 256;
    auto blocks = [](long n, int tb) { return (int)((n + tb - 1) / tb); };
    const int nblk_scan = (M + SCAN_CHUNK - 1) / SCAN_CHUNK;

    cudaMemsetAsync(degi, 0, (size_t)12 * M * sizeof(int));

    // --- degrees + CSR ---------------------------------------------------------
    { dim3 g(blocks(E, TB), NPAIR); count_deg_kernel<<<g, TB>>>(ei, degi, E, M); }
    rsqrt_kernel<<<blocks((long)12 * M, TB), TB>>>(degi, degf, 12 * M);
    { dim3 g(nblk_scan, NPAIR); scanA<<<g, 256>>>(degi, off, bsum, M); }
    scanB<<<NPAIR, MAXBLK>>>(bsum, nblk_scan);
    { dim3 g(blocks(M, TB), NPAIR); scanC<<<g, TB>>>(off, cnt, bsum, M); }
    { dim3 g(blocks(E, TB), NPAIR); fill_adj_kernel<<<g, TB>>>(ei, cnt, adj, E, M); }

    // --- operand splits --------------------------------------------------------
    split_kernel<<<blocks((long)M * DIN, TB), TB>>>(x, ahi, alo, M * DIN);
    split_kernel<<<blocks(NREL * DIN * DH, TB), TB>>>(W1, w1hi, w1lo, NREL * DIN * DH);
    split_kernel<<<blocks(NREL * DH * DOUT, TB), TB>>>(W2, w2hi, w2lo, NREL * DH * DOUT);

    const int gemm_grid = (M + 127) / 128;
    const int gw = blocks((long)M * 32, TB);

    // --- layer 1: z_r = rs_out*(x W1_r); h = sum_r rs_in * gather(z_r); +b; relu
    for (int r = 0; r < NREL; r++) {
        int p = 0 * NREL + r;
        gemm_bf16split<128, 4><<<gemm_grid, 256>>>(
            ahi, alo, w1hi + (size_t)r * DIN * DH, w1lo + (size_t)r * DIN * DH,
            degf + (size_t)(p * 2 + 0) * M, zh, M);
        if (r == 0)
            gather128h<0, false><<<gw, TB>>>(zh, h,
                off + (size_t)p * M, degi + (size_t)(p * 2 + 1) * M,
                adj + (size_t)p * E, degf + (size_t)(p * 2 + 1) * M, b1, M);
        else if (r == 1)
            gather128h<1, false><<<gw, TB>>>(zh, h,
                off + (size_t)p * M, degi + (size_t)(p * 2 + 1) * M,
                adj + (size_t)p * E, degf + (size_t)(p * 2 + 1) * M, b1, M);
        else
            gather128h<2, true><<<gw, TB>>>(zh, h,
                off + (size_t)p * M, degi + (size_t)(p * 2 + 1) * M,
                adj + (size_t)p * E, degf + (size_t)(p * 2 + 1) * M, b1, M);
    }

    // --- layer 2 ----------------------------------------------------------------
    split_kernel<<<blocks((long)M * DH, TB), TB>>>(h, ahi, alo, M * DH);
    for (int r = 0; r < NREL; r++) {
        int p = 1 * NREL + r;
        gemm_bf16split<64, 8><<<gemm_grid, 256>>>(
            ahi, alo, w2hi + (size_t)r * DH * DOUT, w2lo + (size_t)r * DH * DOUT,
            degf + (size_t)(p * 2 + 0) * M, zh, M);
        if (r == 0)
            gather64h<0><<<gw, TB>>>(zh, out,
                off + (size_t)p * M, degi + (size_t)(p * 2 + 1) * M,
                adj + (size_t)p * E, degf + (size_t)(p * 2 + 1) * M, b2, M);
        else if (r == 1)
            gather64h<1><<<gw, TB>>>(zh, out,
                off + (size_t)p * M, degi + (size_t)(p * 2 + 1) * M,
                adj + (size_t)p * E, degf + (size_t)(p * 2 + 1) * M, b2, M);
        else
            gather64h<2><<<gw, TB>>>(zh, out,
                off + (size_t)p * M, degi + (size_t)(p * 2 + 1) * M,
                adj + (size_t)p * E, degf + (size_t)(p * 2 + 1) * M, b2, M);
    }
}

// round 12
// speedup vs baseline: 1.2930x; 1.0351x over previous
#include <cuda_runtime.h>
#include <cuda_bf16.h>
#include <cuda_fp16.h>
#include <mma.h>
#include <cstdint>

using namespace nvcuda;

// ---------------- problem constants ------------------------------------------
#define NMAX   100000
#define EMAX   1600000
#define DIN    128
#define DH     128
#define DOUT   64
#define NREL   3
#define NPAIR  6
#define SCAN_CHUNK 1024
#define MAXBLK 128

// ---------------- scratch (__device__ globals; no allocation allowed) --------
__device__ __half g_z3[(size_t)NMAX * (NREL * DIN)];   // z slices, stride 384 (L1) / 192 (L2)
__device__ __nv_bfloat16 g_ahi[(size_t)NMAX * DIN];    // split of x / h
__device__ __nv_bfloat16 g_alo[(size_t)NMAX * DIN];
__device__ __nv_bfloat16 g_w1hi[NREL * DIN * DH], g_w1lo[NREL * DIN * DH];
__device__ __nv_bfloat16 g_w2hi[NREL * DH * DOUT], g_w2lo[NREL * DH * DOUT];
__device__ int   g_degi[12 * NMAX];
__device__ float g_degf[12 * NMAX];
__device__ int   g_off [NPAIR * NMAX];
__device__ int   g_cnt [NPAIR * NMAX];
__device__ int   g_adj [(size_t)NPAIR * EMAX];
__device__ int   g_bsum[NPAIR * MAXBLK];

// ---------------- fp32 -> (bf16 hi, bf16 lo) split ---------------------------
__global__ void split_kernel(const float* __restrict__ src,
                             __nv_bfloat16* __restrict__ hi,
                             __nv_bfloat16* __restrict__ lo, int n) {
    int i = blockIdx.x * blockDim.x + threadIdx.x;
    if (i >= n) return;
    float v = __ldg(src + i);
    __nv_bfloat16 h = __float2bfloat16(v);
    hi[i] = h;
    lo[i] = __float2bfloat16(v - __bfloat162float(h));
}

// ---------------- degree counting --------------------------------------------
__global__ void count_deg_kernel(const int* __restrict__ ei, int* __restrict__ degi,
                                 int E, int M) {
    int p = blockIdx.y;
    int e = blockIdx.x * blockDim.x + threadIdx.x;
    if (e >= E) return;
    int s = __ldg(ei + (size_t)(p * 2 + 0) * E + e);
    int d = __ldg(ei + (size_t)(p * 2 + 1) * E + e);
    atomicAdd(degi + (size_t)(p * 2 + 0) * M + s, 1);
    atomicAdd(degi + (size_t)(p * 2 + 1) * M + d, 1);
}

__global__ void rsqrt_kernel(const int* __restrict__ degi, float* __restrict__ degf, int n) {
    int i = blockIdx.x * blockDim.x + threadIdx.x;
    if (i < n) degf[i] = rsqrtf((float)max(degi[i], 1));
}

// ---------------- exclusive scan -> CSR offsets -------------------------------
__global__ __launch_bounds__(256)
void scanA(const int* __restrict__ degi, int* __restrict__ off,
           int* __restrict__ bsum, int M) {
    int p = blockIdx.y;
    const int* deg = degi + (size_t)(p * 2 + 1) * M;
    int* o = off + (size_t)p * M;
    int base = blockIdx.x * SCAN_CHUNK;
    int tid = threadIdx.x;

    int v[4];
    int t = 0;
    #pragma unroll
    for (int k = 0; k < 4; k++) {
        int idx = base + tid * 4 + k;
        v[k] = (idx < M) ? deg[idx] : 0;
        t += v[k];
    }
    __shared__ int sm[256];
    sm[tid] = t;
    __syncthreads();
    #pragma unroll
    for (int ofs = 1; ofs < 256; ofs <<= 1) {
        int u = (tid >= ofs) ? sm[tid - ofs] : 0;
        __syncthreads();
        sm[tid] += u;
        __syncthreads();
    }
    int run = sm[tid] - t;
    #pragma unroll
    for (int k = 0; k < 4; k++) {
        int idx = base + tid * 4 + k;
        if (idx < M) o[idx] = run;
        run += v[k];
    }
    if (tid == 255) bsum[p * MAXBLK + blockIdx.x] = sm[255];
}

__global__ __launch_bounds__(MAXBLK)
void scanB(int* __restrict__ bsum, int nblk) {
    int p = blockIdx.x;
    int tid = threadIdx.x;
    int* b = bsum + p * MAXBLK;
    int t = (tid < nblk) ? b[tid] : 0;
    __shared__ int sm[MAXBLK];
    sm[tid] = t;
    __syncthreads();
    #pragma unroll
    for (int ofs = 1; ofs < MAXBLK; ofs <<= 1) {
        int u = (tid >= ofs) ? sm[tid - ofs] : 0;
        __syncthreads();
        sm[tid] += u;
        __syncthreads();
    }
    if (tid < nblk) b[tid] = sm[tid] - t;
}

__global__ void scanC(int* __restrict__ off, int* __restrict__ cnt,
                      const int* __restrict__ bsum, int M) {
    int p = blockIdx.y;
    int i = blockIdx.x * blockDim.x + threadIdx.x;
    if (i < M) {
        int v = off[(size_t)p * M + i] + bsum[p * MAXBLK + (i >> 10)];
        off[(size_t)p * M + i] = v;
        cnt[(size_t)p * M + i] = v;
    }
}

__global__ void fill_adj_kernel(const int* __restrict__ ei,
                                int* __restrict__ cnt, int* __restrict__ adj,
                                int E, int M) {
    int p = blockIdx.y;
    int e = blockIdx.x * blockDim.x + threadIdx.x;
    if (e >= E) return;
    int s = __ldg(ei + (size_t)(p * 2 + 0) * E + e);
    int d = __ldg(ei + (size_t)(p * 2 + 1) * E + e);
    int pos = atomicAdd(cnt + (size_t)p * M + d, 1);
    adj[(size_t)p * E + pos] = s;
}

// ---------------- bf16-split tensor-core GEMM, fp16 output -------------------
#define A_STRIDE 40
#define B_STRIDE 136
#define EPI_STRIDE 68

template<int BN, int WROWS, bool SCALE>
__global__ __launch_bounds__(256)
void gemm_bf16split(const __nv_bfloat16* __restrict__ Ahi,
                    const __nv_bfloat16* __restrict__ Alo,
                    const __nv_bfloat16* __restrict__ Bhi,
                    const __nv_bfloat16* __restrict__ Blo,
                    const float* __restrict__ rs,
                    __half* __restrict__ C, int ldc, int M) {
    constexpr int BM = 128;
    constexpr int BK = 32;
    constexpr int MT = BM / WROWS / 16;

    __shared__ __align__(16) char smem[38912];
    __nv_bfloat16* sAhi = reinterpret_cast<__nv_bfloat16*>(smem);
    __nv_bfloat16* sAlo = sAhi + BM * A_STRIDE;
    __nv_bfloat16* sBhi = reinterpret_cast<__nv_bfloat16*>(smem + 20480);
    __nv_bfloat16* sBlo = sBhi + BK * B_STRIDE;

    const int tid  = threadIdx.x;
    const int w    = tid >> 5;
    const int lane = tid & 31;
    const int warp_row = w % WROWS;
    const int warp_col = w / WROWS;
    const int m_off = warp_row * (BM / WROWS);
    const int n_off = warp_col * 64;
    const int row0 = blockIdx.x * BM;

    wmma::fragment<wmma::accumulator, 16, 16, 16, float> acc[MT][4];
    #pragma unroll
    for (int mt = 0; mt < MT; mt++)
        #pragma unroll
        for (int n = 0; n < 4; n++) wmma::fill_fragment(acc[mt][n], 0.0f);

    for (int kc = 0; kc < 128; kc += BK) {
        if (kc) __syncthreads();
        #pragma unroll
        for (int i = 0; i < 2; i++) {
            int slot = tid + i * 256;
            int r  = slot >> 2;
            int c8 = (slot & 3) * 8;
            int gr = row0 + r;
            uint4 vh = make_uint4(0, 0, 0, 0), vl = make_uint4(0, 0, 0, 0);
            if (gr < M) {
                vh = *reinterpret_cast<const uint4*>(Ahi + (size_t)gr * 128 + kc + c8);
                vl = *reinterpret_cast<const uint4*>(Alo + (size_t)gr * 128 + kc + c8);
            }
            *reinterpret_cast<uint4*>(sAhi + r * A_STRIDE + c8) = vh;
            *reinterpret_cast<uint4*>(sAlo + r * A_STRIDE + c8) = vl;
        }
        constexpr int BSLOT = BK * BN / 8;
        #pragma unroll
        for (int i = 0; i < BSLOT / 256; i++) {
            int slot = tid + i * 256;
            int r  = slot / (BN / 8);
            int c8 = (slot % (BN / 8)) * 8;
            *reinterpret_cast<uint4*>(sBhi + r * B_STRIDE + c8) =
                *reinterpret_cast<const uint4*>(Bhi + (size_t)(kc + r) * BN + c8);
            *reinterpret_cast<uint4*>(sBlo + r * B_STRIDE + c8) =
                *reinterpret_cast<const uint4*>(Blo + (size_t)(kc + r) * BN + c8);
        }
        __syncthreads();

        #pragma unroll
        for (int ks = 0; ks < BK; ks += 16) {
            wmma::fragment<wmma::matrix_a, 16, 16, 16, __nv_bfloat16, wmma::row_major> ahi[MT], alo[MT];
            wmma::fragment<wmma::matrix_b, 16, 16, 16, __nv_bfloat16, wmma::row_major> bhi[4], blo[4];
            #pragma unroll
            for (int mt = 0; mt < MT; mt++) {
                wmma::load_matrix_sync(ahi[mt], sAhi + (m_off + mt * 16) * A_STRIDE + ks, A_STRIDE);
                wmma::load_matrix_sync(alo[mt], sAlo + (m_off + mt * 16) * A_STRIDE + ks, A_STRIDE);
            }
            #pragma unroll
            for (int n = 0; n < 4; n++) {
                wmma::load_matrix_sync(bhi[n], sBhi + ks * B_STRIDE + n_off + n * 16, B_STRIDE);
                wmma::load_matrix_sync(blo[n], sBlo + ks * B_STRIDE + n_off + n * 16, B_STRIDE);
            }
            #pragma unroll
            for (int mt = 0; mt < MT; mt++)
                #pragma unroll
                for (int n = 0; n < 4; n++) {
                    wmma::mma_sync(acc[mt][n], ahi[mt], bhi[n], acc[mt][n]);
                    wmma::mma_sync(acc[mt][n], ahi[mt], blo[n], acc[mt][n]);
                    wmma::mma_sync(acc[mt][n], alo[mt], bhi[n], acc[mt][n]);
                }
        }
    }

    __syncthreads();
    float* epi = reinterpret_cast<float*>(smem + w * 16 * EPI_STRIDE * 4);
    #pragma unroll
    for (int mt = 0; mt < MT; mt++) {
        #pragma unroll
        for (int n = 0; n < 4; n++)
            wmma::store_matrix_sync(epi + n * 16, acc[mt][n], EPI_STRIDE, wmma::mem_row_major);
        __syncwarp();
        int gr0 = row0 + m_off + mt * 16;
        #pragma unroll
        for (int it = 0; it < 8; it++) {
            int idx = it * 32 + lane;
            int r  = idx >> 4;
            int c4 = (idx & 15) * 4;
            int gr = gr0 + r;
            if (gr < M) {
                float s = SCALE ? __ldg(rs + gr) : 1.0f;
                float4 v = *reinterpret_cast<float4*>(epi + r * EPI_STRIDE + c4);
                __half2 p0 = __floats2half2_rn(v.x * s, v.y * s);
                __half2 p1 = __floats2half2_rn(v.z * s, v.w * s);
                uint2 o;
                o.x = *reinterpret_cast<uint32_t*>(&p0);
                o.y = *reinterpret_cast<uint32_t*>(&p1);
                *reinterpret_cast<uint2*>(C + (size_t)gr * ldc + n_off + c4) = o;
            }
        }
        __syncwarp();
    }
}

// ---------------- fused 3-relation gathers ------------------------------------
// Layer 1: h = relu( sum_r rs_in_r[d] * sum_{e in r} rs_out_r[s] * z3[s, r*128:]
//                    + sum_r b1_r )   -> written directly as bf16 hi/lo splits.
__global__ __launch_bounds__(256)
void gatherL1(const __half* __restrict__ z3,
              __nv_bfloat16* __restrict__ ahi, __nv_bfloat16* __restrict__ alo,
              const int* __restrict__ off, const int* __restrict__ degi,
              const int* __restrict__ adj, const float* __restrict__ degf,
              const float* __restrict__ b1, int M, int E) {
    int w = (blockIdx.x * blockDim.x + threadIdx.x) >> 5;
    if (w >= M) return;
    int lane = threadIdx.x & 31;
    float4 tot = make_float4(0.f, 0.f, 0.f, 0.f);

    #pragma unroll
    for (int r = 0; r < NREL; r++) {
        const int*   offp  = off  + (size_t)r * M;
        const int*   degp  = degi + (size_t)(r * 2 + 1) * M;
        const int*   adjp  = adj  + (size_t)r * E;
        const float* rsout = degf + (size_t)(r * 2 + 0) * M;
        const float* rsin  = degf + (size_t)(r * 2 + 1) * M;
        int st = __ldg(offp + w);
        int len = __ldg(degp + w);
        float4 acc = make_float4(0.f, 0.f, 0.f, 0.f);
        const __half* zr = z3 + (size_t)r * 128;
        int j = 0;
        for (; j + 1 < len; j += 2) {
            int s0 = __ldg(adjp + st + j);
            int s1 = __ldg(adjp + st + j + 1);
            float c0 = __ldg(rsout + s0);
            float c1 = __ldg(rsout + s1);
            uint2 r0 = __ldg(reinterpret_cast<const uint2*>(zr + (size_t)s0 * 384 + lane * 4));
            uint2 r1 = __ldg(reinterpret_cast<const uint2*>(zr + (size_t)s1 * 384 + lane * 4));
            float2 a = __half22float2(*reinterpret_cast<__half2*>(&r0.x));
            float2 b = __half22float2(*reinterpret_cast<__half2*>(&r0.y));
            float2 c2 = __half22float2(*reinterpret_cast<__half2*>(&r1.x));
            float2 d2 = __half22float2(*reinterpret_cast<__half2*>(&r1.y));
            acc.x += c0 * a.x + c1 * c2.x; acc.y += c0 * a.y + c1 * c2.y;
            acc.z += c0 * b.x + c1 * d2.x; acc.w += c0 * b.y + c1 * d2.y;
        }
        if (j < len) {
            int s0 = __ldg(adjp + st + j);
            float c0 = __ldg(rsout + s0);
            uint2 r0 = __ldg(reinterpret_cast<const uint2*>(zr + (size_t)s0 * 384 + lane * 4));
            float2 a = __half22float2(*reinterpret_cast<__half2*>(&r0.x));
            float2 b = __half22float2(*reinterpret_cast<__half2*>(&r0.y));
            acc.x += c0 * a.x; acc.y += c0 * a.y;
            acc.z += c0 * b.x; acc.w += c0 * b.y;
        }
        float ci = __ldg(rsin + w);
        tot.x += ci * acc.x; tot.y += ci * acc.y;
        tot.z += ci * acc.z; tot.w += ci * acc.w;
    }

    int col = lane * 4;
    tot.x = fmaxf(tot.x + __ldg(b1 + col + 0) + __ldg(b1 + 128 + col + 0) + __ldg(b1 + 256 + col + 0), 0.f);
    tot.y = fmaxf(tot.y + __ldg(b1 + col + 1) + __ldg(b1 + 128 + col + 1) + __ldg(b1 + 256 + col + 1), 0.f);
    tot.z = fmaxf(tot.z + __ldg(b1 + col + 2) + __ldg(b1 + 128 + col + 2) + __ldg(b1 + 256 + col + 2), 0.f);
    tot.w = fmaxf(tot.w + __ldg(b1 + col + 3) + __ldg(b1 + 128 + col + 3) + __ldg(b1 + 256 + col + 3), 0.f);

    // direct bf16 hi/lo split (layer-2 GEMM operand)
    __nv_bfloat16 hx = __float2bfloat16(tot.x), hy = __float2bfloat16(tot.y);
    __nv_bfloat16 hz = __float2bfloat16(tot.z), hw = __float2bfloat16(tot.w);
    __nv_bfloat16 lx = __float2bfloat16(tot.x - __bfloat162float(hx));
    __nv_bfloat16 ly = __float2bfloat16(tot.y - __bfloat162float(hy));
    __nv_bfloat16 lz = __float2bfloat16(tot.z - __bfloat162float(hz));
    __nv_bfloat16 lw = __float2bfloat16(tot.w - __bfloat162float(hw));
    __nv_bfloat162 h0 = __nv_bfloat162(hx, hy), h1 = __nv_bfloat162(hz, hw);
    __nv_bfloat162 l0 = __nv_bfloat162(lx, ly), l1 = __nv_bfloat162(lz, lw);
    uint2 oh, ol;
    oh.x = *reinterpret_cast<uint32_t*>(&h0); oh.y = *reinterpret_cast<uint32_t*>(&h1);
    ol.x = *reinterpret_cast<uint32_t*>(&l0); ol.y = *reinterpret_cast<uint32_t*>(&l1);
    *reinterpret_cast<uint2*>(ahi + (size_t)w * 128 + col) = oh;
    *reinterpret_cast<uint2*>(alo + (size_t)w * 128 + col) = ol;
}

// Layer 2: out = sum_r rs_in_r[d] * gather(z3[:, r*64:]) + sum_r b2_r
__global__ __launch_bounds__(256)
void gatherL2(const __half* __restrict__ z3, float* __restrict__ out,
              const int* __restrict__ off, const int* __restrict__ degi,
              const int* __restrict__ adj, const float* __restrict__ degf,
              const float* __restrict__ b2, int M, int E) {
    int w = (blockIdx.x * blockDim.x + threadIdx.x) >> 5;
    if (w >= M) return;
    int lane = threadIdx.x & 31;
    float2 tot = make_float2(0.f, 0.f);

    #pragma unroll
    for (int r = 0; r < NREL; r++) {
        int p = NREL + r;
        const int*   offp  = off  + (size_t)p * M;
        const int*   degp  = degi + (size_t)(p * 2 + 1) * M;
        const int*   adjp  = adj  + (size_t)p * E;
        const float* rsin  = degf + (size_t)(p * 2 + 1) * M;
        int st = __ldg(offp + w);
        int len = __ldg(degp + w);
        float2 acc = make_float2(0.f, 0.f);
        const __half* zr = z3 + (size_t)r * 64;
        int j = 0;
        for (; j + 1 < len; j += 2) {
            int s0 = __ldg(adjp + st + j);
            int s1 = __ldg(adjp + st + j + 1);
            uint32_t r0 = __ldg(reinterpret_cast<const uint32_t*>(zr + (size_t)s0 * 192 + lane * 2));
            uint32_t r1 = __ldg(reinterpret_cast<const uint32_t*>(zr + (size_t)s1 * 192 + lane * 2));
            float2 a = __half22float2(*reinterpret_cast<__half2*>(&r0));
            float2 b = __half22float2(*reinterpret_cast<__half2*>(&r1));
            acc.x += a.x + b.x; acc.y += a.y + b.y;
        }
        if (j < len) {
            int s0 = __ldg(adjp + st + j);
            uint32_t r0 = __ldg(reinterpret_cast<const uint32_t*>(zr + (size_t)s0 * 192 + lane * 2));
            float2 a = __half22float2(*reinterpret_cast<__half2*>(&r0));
            acc.x += a.x; acc.y += a.y;
        }
        float ci = __ldg(rsin + w);
        tot.x += ci * acc.x; tot.y += ci * acc.y;
    }

    int col = lane * 2;
    tot.x += __ldg(b2 + col + 0) + __ldg(b2 + 64 + col + 0) + __ldg(b2 + 128 + col + 0);
    tot.y += __ldg(b2 + col + 1) + __ldg(b2 + 64 + col + 1) + __ldg(b2 + 128 + col + 1);
    *reinterpret_cast<float2*>(out + (size_t)w * 64 + col) = tot;
}

// ---------------- orchestration ----------------------------------------------
extern "C" void kernel_launch(void* const* d_in, const int* in_sizes, int n_in,
                              void* d_out, int out_size) {
    const float* x  = (const float*)d_in[0];
    const float* W1 = (const float*)d_in[1];
    const float* b1 = (const float*)d_in[2];
    const float* W2 = (const float*)d_in[3];
    const float* b2 = (const float*)d_in[4];
    const int*   ei = (const int*)d_in[5];
    float* out = (float*)d_out;

    const int M = in_sizes[0] / DIN;
    const int E = in_sizes[5] / (2 * NREL * 2);

    float* degf;
    __half* z3;
    __nv_bfloat16 *ahi, *alo, *w1hi, *w1lo, *w2hi, *w2lo;
    int *degi, *off, *cnt, *adj, *bsum;
    cudaGetSymbolAddress((void**)&z3,   g_z3);
    cudaGetSymbolAddress((void**)&ahi,  g_ahi);
    cudaGetSymbolAddress((void**)&alo,  g_alo);
    cudaGetSymbolAddress((void**)&w1hi, g_w1hi);
    cudaGetSymbolAddress((void**)&w1lo, g_w1lo);
    cudaGetSymbolAddress((void**)&w2hi, g_w2hi);
    cudaGetSymbolAddress((void**)&w2lo, g_w2lo);
    cudaGetSymbolAddress((void**)&degf, g_degf);
    cudaGetSymbolAddress((void**)&degi, g_degi);
    cudaGetSymbolAddress((void**)&off,  g_off);
    cudaGetSymbolAddress((void**)&cnt,  g_cnt);
    cudaGetSymbolAddress((void**)&adj,  g_adj);
    cudaGetSymbolAddress((void**)&bsum, g_bsum);

    const int TB = 256;
    auto blocks = [](long n, int tb) { return (int)((n + tb - 1) / tb); };
    const int nblk_scan = (M + SCAN_CHUNK - 1) / SCAN_CHUNK;
    const int gemm_grid = (M + 127) / 128;
    const int gw = blocks((long)M * 32, TB);

    // ---- fork a side stream for the CSR build (captured via events) ----------
    cudaStream_t s2;
    cudaStreamCreateWithFlags(&s2, cudaStreamNonBlocking);
    cudaEvent_t evFork, evCsr;
    cudaEventCreateWithFlags(&evFork, cudaEventDisableTiming);
    cudaEventCreateWithFlags(&evCsr,  cudaEventDisableTiming);
    cudaEventRecord(evFork, 0);
    cudaStreamWaitEvent(s2, evFork, 0);

    // ---- main stream: splits + layer-1 GEMMs (degree-independent) ------------
    split_kernel<<<blocks((long)M * DIN, TB), TB>>>(x, ahi, alo, M * DIN);
    split_kernel<<<blocks(NREL * DIN * DH, TB), TB>>>(W1, w1hi, w1lo, NREL * DIN * DH);
    split_kernel<<<blocks(NREL * DH * DOUT, TB), TB>>>(W2, w2hi, w2lo, NREL * DH * DOUT);
    for (int r = 0; r < NREL; r++)
        gemm_bf16split<128, 4, false><<<gemm_grid, 256>>>(
            ahi, alo, w1hi + (size_t)r * DIN * DH, w1lo + (size_t)r * DIN * DH,
            nullptr, z3 + (size_t)r * 128, NREL * DIN, M);

    // ---- side stream: degrees + CSR -------------------------------------------
    cudaMemsetAsync(degi, 0, (size_t)12 * M * sizeof(int), s2);
    { dim3 g(blocks(E, TB), NPAIR); count_deg_kernel<<<g, TB, 0, s2>>>(ei, degi, E, M); }
    rsqrt_kernel<<<blocks((long)12 * M, TB), TB, 0, s2>>>(degi, degf, 12 * M);
    { dim3 g(nblk_scan, NPAIR); scanA<<<g, 256, 0, s2>>>(degi, off, bsum, M); }
    scanB<<<NPAIR, MAXBLK, 0, s2>>>(bsum, nblk_scan);
    { dim3 g(blocks(M, TB), NPAIR); scanC<<<g, TB, 0, s2>>>(off, cnt, bsum, M); }
    { dim3 g(blocks(E, TB), NPAIR); fill_adj_kernel<<<g, TB, 0, s2>>>(ei, cnt, adj, E, M); }
    cudaEventRecord(evCsr, s2);

    // ---- join, then aggregation + layer 2 -------------------------------------
    cudaStreamWaitEvent(0, evCsr, 0);
    gatherL1<<<gw, TB>>>(z3, ahi, alo, off, degi, adj, degf, b1, M, E);

    for (int r = 0; r < NREL; r++) {
        int p = NREL + r;
        gemm_bf16split<64, 8, true><<<gemm_grid, 256>>>(
            ahi, alo, w2hi + (size_t)r * DH * DOUT, w2lo + (size_t)r * DH * DOUT,
            degf + (size_t)(p * 2 + 0) * M, z3 + (size_t)r * 64, NREL * DOUT, M);
    }
    gatherL2<<<gw, TB>>>(z3, out, off, degi, adj, degf, b2, M, E);

    cudaStreamDestroy(s2);
    cudaEventDestroy(evFork);
    cudaEventDestroy(evCsr);
}

// round 13
// speedup vs baseline: 1.3494x; 1.0436x over previous
#include <cuda_runtime.h>
#include <cuda_bf16.h>
#include <cuda_fp16.h>
#include <mma.h>
#include <cstdint>

using namespace nvcuda;

// ---------------- problem constants ------------------------------------------
#define NMAX   100000
#define EMAX   1600000
#define DIN    128
#define DH     128
#define DOUT   64
#define NREL   3
#define NPAIR  6
#define SCAN_CHUNK 1024
#define MAXBLK 128

// ---------------- scratch (__device__ globals; no allocation allowed) --------
__device__ __align__(128) __half g_z3[(size_t)NMAX * (NREL * DIN)];
__device__ __align__(128) __nv_bfloat16 g_ahi[(size_t)NMAX * DIN];
__device__ __align__(128) __nv_bfloat16 g_alo[(size_t)NMAX * DIN];
__device__ __align__(128) __nv_bfloat16 g_w1hi[NREL * DIN * DH], g_w1lo[NREL * DIN * DH];
__device__ __align__(128) __nv_bfloat16 g_w2hi[NREL * DH * DOUT], g_w2lo[NREL * DH * DOUT];
__device__ int   g_degi[12 * NMAX];
__device__ float g_degf[12 * NMAX];
__device__ int   g_off [NPAIR * NMAX];
__device__ int   g_cnt [NPAIR * NMAX];
__device__ int   g_adj [(size_t)NPAIR * EMAX];
__device__ int   g_bsum[NPAIR * MAXBLK];

// ---------------- cp.async helpers -------------------------------------------
__device__ __forceinline__ void cpa16(void* smem, const void* g, bool valid) {
    uint32_t s = (uint32_t)__cvta_generic_to_shared(smem);
    int sz = valid ? 16 : 0;
    asm volatile("cp.async.cg.shared.global [%0], [%1], 16, %2;\n"
                 :: "r"(s), "l"(g), "r"(sz));
}
__device__ __forceinline__ void cpa_commit() {
    asm volatile("cp.async.commit_group;\n" ::: "memory");
}
__device__ __forceinline__ void cpa_wait0() {
    asm volatile("cp.async.wait_group 0;\n" ::: "memory");
}

// ---------------- fp32 -> (bf16 hi, bf16 lo) split ---------------------------
__global__ void split_kernel(const float* __restrict__ src,
                             __nv_bfloat16* __restrict__ hi,
                             __nv_bfloat16* __restrict__ lo, int n) {
    int i = blockIdx.x * blockDim.x + threadIdx.x;
    if (i >= n) return;
    float v = __ldg(src + i);
    __nv_bfloat16 h = __float2bfloat16(v);
    hi[i] = h;
    lo[i] = __float2bfloat16(v - __bfloat162float(h));
}

// ---------------- degree counting (pbase selects pair range) ------------------
__global__ void count_deg_kernel(const int* __restrict__ ei, int* __restrict__ degi,
                                 int E, int M, int pbase) {
    int p = pbase + blockIdx.y;
    int e = blockIdx.x * blockDim.x + threadIdx.x;
    if (e >= E) return;
    int s = __ldg(ei + (size_t)(p * 2 + 0) * E + e);
    int d = __ldg(ei + (size_t)(p * 2 + 1) * E + e);
    atomicAdd(degi + (size_t)(p * 2 + 0) * M + s, 1);
    atomicAdd(degi + (size_t)(p * 2 + 1) * M + d, 1);
}

__global__ void rsqrt_kernel(const int* __restrict__ degi, float* __restrict__ degf, int n) {
    int i = blockIdx.x * blockDim.x + threadIdx.x;
    if (i < n) degf[i] = rsqrtf((float)max(degi[i], 1));
}

// ---------------- exclusive scan -> CSR offsets -------------------------------
__global__ __launch_bounds__(256)
void scanA(const int* __restrict__ degi, int* __restrict__ off,
           int* __restrict__ bsum, int M, int pbase) {
    int p = pbase + blockIdx.y;
    const int* deg = degi + (size_t)(p * 2 + 1) * M;
    int* o = off + (size_t)p * M;
    int base = blockIdx.x * SCAN_CHUNK;
    int tid = threadIdx.x;

    int v[4];
    int t = 0;
    #pragma unroll
    for (int k = 0; k < 4; k++) {
        int idx = base + tid * 4 + k;
        v[k] = (idx < M) ? deg[idx] : 0;
        t += v[k];
    }
    __shared__ int sm[256];
    sm[tid] = t;
    __syncthreads();
    #pragma unroll
    for (int ofs = 1; ofs < 256; ofs <<= 1) {
        int u = (tid >= ofs) ? sm[tid - ofs] : 0;
        __syncthreads();
        sm[tid] += u;
        __syncthreads();
    }
    int run = sm[tid] - t;
    #pragma unroll
    for (int k = 0; k < 4; k++) {
        int idx = base + tid * 4 + k;
        if (idx < M) o[idx] = run;
        run += v[k];
    }
    if (tid == 255) bsum[p * MAXBLK + blockIdx.x] = sm[255];
}

__global__ __launch_bounds__(MAXBLK)
void scanB(int* __restrict__ bsum, int nblk, int pbase) {
    int p = pbase + blockIdx.x;
    int tid = threadIdx.x;
    int* b = bsum + p * MAXBLK;
    int t = (tid < nblk) ? b[tid] : 0;
    __shared__ int sm[MAXBLK];
    sm[tid] = t;
    __syncthreads();
    #pragma unroll
    for (int ofs = 1; ofs < MAXBLK; ofs <<= 1) {
        int u = (tid >= ofs) ? sm[tid - ofs] : 0;
        __syncthreads();
        sm[tid] += u;
        __syncthreads();
    }
    if (tid < nblk) b[tid] = sm[tid] - t;
}

__global__ void scanC(int* __restrict__ off, int* __restrict__ cnt,
                      const int* __restrict__ bsum, int M, int pbase) {
    int p = pbase + blockIdx.y;
    int i = blockIdx.x * blockDim.x + threadIdx.x;
    if (i < M) {
        int v = off[(size_t)p * M + i] + bsum[p * MAXBLK + (i >> 10)];
        off[(size_t)p * M + i] = v;
        cnt[(size_t)p * M + i] = v;
    }
}

__global__ void fill_adj_kernel(const int* __restrict__ ei,
                                int* __restrict__ cnt, int* __restrict__ adj,
                                int E, int M, int pbase) {
    int p = pbase + blockIdx.y;
    int e = blockIdx.x * blockDim.x + threadIdx.x;
    if (e >= E) return;
    int s = __ldg(ei + (size_t)(p * 2 + 0) * E + e);
    int d = __ldg(ei + (size_t)(p * 2 + 1) * E + e);
    int pos = atomicAdd(cnt + (size_t)p * M + d, 1);
    adj[(size_t)p * E + pos] = s;
}

// ---------------- relation-fused, double-buffered bf16-split GEMM ------------
// C[M, NREL*BN] : for each r, C[:, r*BN:(r+1)*BN] = scale_r * (A @ B_r)
// A in smem once (hi+lo, 128 rows x 128 cols); B chunks double-buffered cp.async.
#define A_ST 136                 // A smem stride (bf16 elems)
#define EPI_ST 68                // epilogue stride (fp32)

template<int BN, bool SCALE>
__global__ __launch_bounds__(256)
void gemm_fused(const __nv_bfloat16* __restrict__ Ahi,
                const __nv_bfloat16* __restrict__ Alo,
                const __nv_bfloat16* __restrict__ Bhi,   // [NREL][128][BN]
                const __nv_bfloat16* __restrict__ Blo,
                const float* __restrict__ rsbase,        // rs_r = rsbase + r*2*M
                __half* __restrict__ C, int M) {
    constexpr int LDC = NREL * BN;
    constexpr int WROWS = (BN == 128) ? 4 : 8;
    constexpr int MT = 128 / WROWS / 16;
    constexpr int BST = BN + 8;
    constexpr int KCH = 4;                    // 128 / 32
    constexpr int TOT = NREL * KCH;
    constexpr int BXF = 32 * BN / 8;          // 16B xfers per (hi|lo) B chunk

    extern __shared__ __align__(16) char dsm[];
    __nv_bfloat16* sAhi = reinterpret_cast<__nv_bfloat16*>(dsm);
    __nv_bfloat16* sAlo = sAhi + 128 * A_ST;
    __nv_bfloat16* sB   = sAlo + 128 * A_ST;  // [2 stages][hi,lo][32*BST]
    float* epiBase = reinterpret_cast<float*>(sB + 2 * 2 * 32 * BST);

    const int tid  = threadIdx.x;
    const int w    = tid >> 5;
    const int lane = tid & 31;
    const int warp_row = w % WROWS;
    const int warp_col = w / WROWS;
    const int m_off = warp_row * (128 / WROWS);
    const int n_off = warp_col * 64;
    const int row0 = blockIdx.x * 128;

    // ---- A: one-time cp.async load (hi + lo), zero-fill rows >= M ----------
    #pragma unroll
    for (int i = 0; i < 8; i++) {
        int slot = tid + i * 256;
        int r = slot >> 4;
        int c = (slot & 15) * 8;
        int gr = row0 + r;
        bool valid = gr < M;
        const __nv_bfloat16* gh = Ahi + (size_t)gr * 128 + c;
        const __nv_bfloat16* gl = Alo + (size_t)gr * 128 + c;
        cpa16(sAhi + r * A_ST + c, valid ? gh : (const void*)Ahi, valid);
        cpa16(sAlo + r * A_ST + c, valid ? gl : (const void*)Alo, valid);
    }

    auto loadB = [&](int it, int st) {
        int rel = it / KCH;
        int kc = (it % KCH) * 32;
        __nv_bfloat16* dh = sB + st * 2 * 32 * BST;
        __nv_bfloat16* dl = dh + 32 * BST;
        const __nv_bfloat16* gh = Bhi + (size_t)rel * 128 * BN;
        const __nv_bfloat16* gl = Blo + (size_t)rel * 128 * BN;
        #pragma unroll
        for (int i = 0; i < BXF / 256; i++) {
            int slot = tid + i * 256;
            int r = slot / (BN / 8);
            int c = (slot % (BN / 8)) * 8;
            cpa16(dh + r * BST + c, gh + (size_t)(kc + r) * BN + c, true);
            cpa16(dl + r * BST + c, gl + (size_t)(kc + r) * BN + c, true);
        }
    };
    loadB(0, 0);
    cpa_commit();

    wmma::fragment<wmma::accumulator, 16, 16, 16, float> acc[MT][4];
    #pragma unroll
    for (int mt = 0; mt < MT; mt++)
        #pragma unroll
        for (int n = 0; n < 4; n++) wmma::fill_fragment(acc[mt][n], 0.0f);

    for (int it = 0; it < TOT; it++) {
        cpa_wait0();
        __syncthreads();
        if (it + 1 < TOT) { loadB(it + 1, (it + 1) & 1); cpa_commit(); }

        const int cur = it & 1;
        const int kc = (it % KCH) * 32;
        const __nv_bfloat16* bh = sB + cur * 2 * 32 * BST;
        const __nv_bfloat16* bl = bh + 32 * BST;

        #pragma unroll
        for (int ks = 0; ks < 32; ks += 16) {
            wmma::fragment<wmma::matrix_a, 16, 16, 16, __nv_bfloat16, wmma::row_major> fahi[MT], falo[MT];
            wmma::fragment<wmma::matrix_b, 16, 16, 16, __nv_bfloat16, wmma::row_major> fbhi[4], fblo[4];
            #pragma unroll
            for (int mt = 0; mt < MT; mt++) {
                wmma::load_matrix_sync(fahi[mt], sAhi + (m_off + mt * 16) * A_ST + kc + ks, A_ST);
                wmma::load_matrix_sync(falo[mt], sAlo + (m_off + mt * 16) * A_ST + kc + ks, A_ST);
            }
            #pragma unroll
            for (int n = 0; n < 4; n++) {
                wmma::load_matrix_sync(fbhi[n], bh + ks * BST + n_off + n * 16, BST);
                wmma::load_matrix_sync(fblo[n], bl + ks * BST + n_off + n * 16, BST);
            }
            #pragma unroll
            for (int mt = 0; mt < MT; mt++)
                #pragma unroll
                for (int n = 0; n < 4; n++) {
                    wmma::mma_sync(acc[mt][n], fahi[mt], fbhi[n], acc[mt][n]);
                    wmma::mma_sync(acc[mt][n], fahi[mt], fblo[n], acc[mt][n]);
                    wmma::mma_sync(acc[mt][n], falo[mt], fbhi[n], acc[mt][n]);
                }
        }

        if ((it % KCH) == KCH - 1) {
            // epilogue for relation rel
            int rel = it / KCH;
            const float* rs = rsbase + (size_t)rel * 2 * M;
            float* epi = epiBase + w * 16 * EPI_ST;
            #pragma unroll
            for (int mt = 0; mt < MT; mt++) {
                #pragma unroll
                for (int n = 0; n < 4; n++)
                    wmma::store_matrix_sync(epi + n * 16, acc[mt][n], EPI_ST, wmma::mem_row_major);
                __syncwarp();
                int gr0 = row0 + m_off + mt * 16;
                #pragma unroll
                for (int itc = 0; itc < 8; itc++) {
                    int idx = itc * 32 + lane;
                    int r = idx >> 4;
                    int c4 = (idx & 15) * 4;
                    int gr = gr0 + r;
                    if (gr < M) {
                        float s = SCALE ? __ldg(rs + gr) : 1.0f;
                        float4 v = *reinterpret_cast<float4*>(epi + r * EPI_ST + c4);
                        __half2 p0 = __floats2half2_rn(v.x * s, v.y * s);
                        __half2 p1 = __floats2half2_rn(v.z * s, v.w * s);
                        uint2 o;
                        o.x = *reinterpret_cast<uint32_t*>(&p0);
                        o.y = *reinterpret_cast<uint32_t*>(&p1);
                        *reinterpret_cast<uint2*>(C + (size_t)gr * LDC + rel * BN + n_off + c4) = o;
                    }
                }
                __syncwarp();
            }
            #pragma unroll
            for (int mt = 0; mt < MT; mt++)
                #pragma unroll
                for (int n = 0; n < 4; n++) wmma::fill_fragment(acc[mt][n], 0.0f);
        }
    }
}

// ---------------- fused 3-relation gathers ------------------------------------
__global__ __launch_bounds__(256)
void gatherL1(const __half* __restrict__ z3,
              __nv_bfloat16* __restrict__ ahi, __nv_bfloat16* __restrict__ alo,
              const int* __restrict__ off, const int* __restrict__ degi,
              const int* __restrict__ adj, const float* __restrict__ degf,
              const float* __restrict__ b1, int M, int E) {
    int w = (blockIdx.x * blockDim.x + threadIdx.x) >> 5;
    if (w >= M) return;
    int lane = threadIdx.x & 31;
    float4 tot = make_float4(0.f, 0.f, 0.f, 0.f);

    #pragma unroll
    for (int r = 0; r < NREL; r++) {
        const int*   offp  = off  + (size_t)r * M;
        const int*   degp  = degi + (size_t)(r * 2 + 1) * M;
        const int*   adjp  = adj  + (size_t)r * E;
        const float* rsout = degf + (size_t)(r * 2 + 0) * M;
        const float* rsin  = degf + (size_t)(r * 2 + 1) * M;
        int st = __ldg(offp + w);
        int len = __ldg(degp + w);
        float4 acc = make_float4(0.f, 0.f, 0.f, 0.f);
        const __half* zr = z3 + (size_t)r * 128;
        int j = 0;
        for (; j + 1 < len; j += 2) {
            int s0 = __ldg(adjp + st + j);
            int s1 = __ldg(adjp + st + j + 1);
            float c0 = __ldg(rsout + s0);
            float c1 = __ldg(rsout + s1);
            uint2 r0 = __ldg(reinterpret_cast<const uint2*>(zr + (size_t)s0 * 384 + lane * 4));
            uint2 r1 = __ldg(reinterpret_cast<const uint2*>(zr + (size_t)s1 * 384 + lane * 4));
            float2 a = __half22float2(*reinterpret_cast<__half2*>(&r0.x));
            float2 b = __half22float2(*reinterpret_cast<__half2*>(&r0.y));
            float2 c2 = __half22float2(*reinterpret_cast<__half2*>(&r1.x));
            float2 d2 = __half22float2(*reinterpret_cast<__half2*>(&r1.y));
            acc.x += c0 * a.x + c1 * c2.x; acc.y += c0 * a.y + c1 * c2.y;
            acc.z += c0 * b.x + c1 * d2.x; acc.w += c0 * b.y + c1 * d2.y;
        }
        if (j < len) {
            int s0 = __ldg(adjp + st + j);
            float c0 = __ldg(rsout + s0);
            uint2 r0 = __ldg(reinterpret_cast<const uint2*>(zr + (size_t)s0 * 384 + lane * 4));
            float2 a = __half22float2(*reinterpret_cast<__half2*>(&r0.x));
            float2 b = __half22float2(*reinterpret_cast<__half2*>(&r0.y));
            acc.x += c0 * a.x; acc.y += c0 * a.y;
            acc.z += c0 * b.x; acc.w += c0 * b.y;
        }
        float ci = __ldg(rsin + w);
        tot.x += ci * acc.x; tot.y += ci * acc.y;
        tot.z += ci * acc.z; tot.w += ci * acc.w;
    }

    int col = lane * 4;
    tot.x = fmaxf(tot.x + __ldg(b1 + col + 0) + __ldg(b1 + 128 + col + 0) + __ldg(b1 + 256 + col + 0), 0.f);
    tot.y = fmaxf(tot.y + __ldg(b1 + col + 1) + __ldg(b1 + 128 + col + 1) + __ldg(b1 + 256 + col + 1), 0.f);
    tot.z = fmaxf(tot.z + __ldg(b1 + col + 2) + __ldg(b1 + 128 + col + 2) + __ldg(b1 + 256 + col + 2), 0.f);
    tot.w = fmaxf(tot.w + __ldg(b1 + col + 3) + __ldg(b1 + 128 + col + 3) + __ldg(b1 + 256 + col + 3), 0.f);

    __nv_bfloat16 hx = __float2bfloat16(tot.x), hy = __float2bfloat16(tot.y);
    __nv_bfloat16 hz = __float2bfloat16(tot.z), hw = __float2bfloat16(tot.w);
    __nv_bfloat16 lx = __float2bfloat16(tot.x - __bfloat162float(hx));
    __nv_bfloat16 ly = __float2bfloat16(tot.y - __bfloat162float(hy));
    __nv_bfloat16 lz = __float2bfloat16(tot.z - __bfloat162float(hz));
    __nv_bfloat16 lw = __float2bfloat16(tot.w - __bfloat162float(hw));
    __nv_bfloat162 h0 = __nv_bfloat162(hx, hy), h1 = __nv_bfloat162(hz, hw);
    __nv_bfloat162 l0 = __nv_bfloat162(lx, ly), l1 = __nv_bfloat162(lz, lw);
    uint2 oh, ol;
    oh.x = *reinterpret_cast<uint32_t*>(&h0); oh.y = *reinterpret_cast<uint32_t*>(&h1);
    ol.x = *reinterpret_cast<uint32_t*>(&l0); ol.y = *reinterpret_cast<uint32_t*>(&l1);
    *reinterpret_cast<uint2*>(ahi + (size_t)w * 128 + col) = oh;
    *reinterpret_cast<uint2*>(alo + (size_t)w * 128 + col) = ol;
}

__global__ __launch_bounds__(256)
void gatherL2(const __half* __restrict__ z3, float* __restrict__ out,
              const int* __restrict__ off, const int* __restrict__ degi,
              const int* __restrict__ adj, const float* __restrict__ degf,
              const float* __restrict__ b2, int M, int E) {
    int w = (blockIdx.x * blockDim.x + threadIdx.x) >> 5;
    if (w >= M) return;
    int lane = threadIdx.x & 31;
    float2 tot = make_float2(0.f, 0.f);

    #pragma unroll
    for (int r = 0; r < NREL; r++) {
        int p = NREL + r;
        const int*   offp  = off  + (size_t)p * M;
        const int*   degp  = degi + (size_t)(p * 2 + 1) * M;
        const int*   adjp  = adj  + (size_t)p * E;
        const float* rsin  = degf + (size_t)(p * 2 + 1) * M;
        int st = __ldg(offp + w);
        int len = __ldg(degp + w);
        float2 acc = make_float2(0.f, 0.f);
        const __half* zr = z3 + (size_t)r * 64;
        int j = 0;
        for (; j + 1 < len; j += 2) {
            int s0 = __ldg(adjp + st + j);
            int s1 = __ldg(adjp + st + j + 1);
            uint32_t r0 = __ldg(reinterpret_cast<const uint32_t*>(zr + (size_t)s0 * 192 + lane * 2));
            uint32_t r1 = __ldg(reinterpret_cast<const uint32_t*>(zr + (size_t)s1 * 192 + lane * 2));
            float2 a = __half22float2(*reinterpret_cast<__half2*>(&r0));
            float2 b = __half22float2(*reinterpret_cast<__half2*>(&r1));
            acc.x += a.x + b.x; acc.y += a.y + b.y;
        }
        if (j < len) {
            int s0 = __ldg(adjp + st + j);
            uint32_t r0 = __ldg(reinterpret_cast<const uint32_t*>(zr + (size_t)s0 * 192 + lane * 2));
            float2 a = __half22float2(*reinterpret_cast<__half2*>(&r0));
            acc.x += a.x; acc.y += a.y;
        }
        float ci = __ldg(rsin + w);
        tot.x += ci * acc.x; tot.y += ci * acc.y;
    }

    int col = lane * 2;
    tot.x += __ldg(b2 + col + 0) + __ldg(b2 + 64 + col + 0) + __ldg(b2 + 128 + col + 0);
    tot.y += __ldg(b2 + col + 1) + __ldg(b2 + 64 + col + 1) + __ldg(b2 + 128 + col + 1);
    *reinterpret_cast<float2*>(out + (size_t)w * 64 + col) = tot;
}

// ---------------- orchestration ----------------------------------------------
extern "C" void kernel_launch(void* const* d_in, const int* in_sizes, int n_in,
                              void* d_out, int out_size) {
    const float* x  = (const float*)d_in[0];
    const float* W1 = (const float*)d_in[1];
    const float* b1 = (const float*)d_in[2];
    const float* W2 = (const float*)d_in[3];
    const float* b2 = (const float*)d_in[4];
    const int*   ei = (const int*)d_in[5];
    float* out = (float*)d_out;

    const int M = in_sizes[0] / DIN;
    const int E = in_sizes[5] / (2 * NREL * 2);

    float* degf;
    __half* z3;
    __nv_bfloat16 *ahi, *alo, *w1hi, *w1lo, *w2hi, *w2lo;
    int *degi, *off, *cnt, *adj, *bsum;
    cudaGetSymbolAddress((void**)&z3,   g_z3);
    cudaGetSymbolAddress((void**)&ahi,  g_ahi);
    cudaGetSymbolAddress((void**)&alo,  g_alo);
    cudaGetSymbolAddress((void**)&w1hi, g_w1hi);
    cudaGetSymbolAddress((void**)&w1lo, g_w1lo);
    cudaGetSymbolAddress((void**)&w2hi, g_w2hi);
    cudaGetSymbolAddress((void**)&w2lo, g_w2lo);
    cudaGetSymbolAddress((void**)&degf, g_degf);
    cudaGetSymbolAddress((void**)&degi, g_degi);
    cudaGetSymbolAddress((void**)&off,  g_off);
    cudaGetSymbolAddress((void**)&cnt,  g_cnt);
    cudaGetSymbolAddress((void**)&adj,  g_adj);
    cudaGetSymbolAddress((void**)&bsum, g_bsum);

    const int TB = 256;
    auto blocks = [](long n, int tb) { return (int)((n + tb - 1) / tb); };
    const int nblk_scan = (M + SCAN_CHUNK - 1) / SCAN_CHUNK;
    const int gemm_grid = (M + 127) / 128;
    const int gw = blocks((long)M * 32, TB);

    // dynamic smem sizes
    const int SMEM_L1 = 128 * A_ST * 2 * 2 + 2 * 2 * 32 * (128 + 8) * 2 + 8 * 16 * EPI_ST * 4;
    const int SMEM_L2 = 128 * A_ST * 2 * 2 + 2 * 2 * 32 * (64 + 8) * 2 + 8 * 16 * EPI_ST * 4;
    cudaFuncSetAttribute(gemm_fused<128, false>,
                         cudaFuncAttributeMaxDynamicSharedMemorySize, SMEM_L1);
    cudaFuncSetAttribute(gemm_fused<64, true>,
                         cudaFuncAttributeMaxDynamicSharedMemorySize, SMEM_L2);

    // ---- fork side stream for CSR build ---------------------------------------
    cudaStream_t s2;
    cudaStreamCreateWithFlags(&s2, cudaStreamNonBlocking);
    cudaEvent_t evFork, evCsr1, evDeg2, evCsr2;
    cudaEventCreateWithFlags(&evFork, cudaEventDisableTiming);
    cudaEventCreateWithFlags(&evCsr1, cudaEventDisableTiming);
    cudaEventCreateWithFlags(&evDeg2, cudaEventDisableTiming);
    cudaEventCreateWithFlags(&evCsr2, cudaEventDisableTiming);
    cudaEventRecord(evFork, 0);
    cudaStreamWaitEvent(s2, evFork, 0);

    // ---- main: splits + fused layer-1 GEMM (degree-independent) ---------------
    split_kernel<<<blocks((long)M * DIN, TB), TB>>>(x, ahi, alo, M * DIN);
    split_kernel<<<blocks(NREL * DIN * DH, TB), TB>>>(W1, w1hi, w1lo, NREL * DIN * DH);
    split_kernel<<<blocks(NREL * DH * DOUT, TB), TB>>>(W2, w2hi, w2lo, NREL * DH * DOUT);
    gemm_fused<128, false><<<gemm_grid, 256, SMEM_L1>>>(
        ahi, alo, w1hi, w1lo, nullptr, z3, M);

    // ---- side: layer-1 CSR, then layer-2 CSR ----------------------------------
    cudaMemsetAsync(degi, 0, (size_t)12 * M * sizeof(int), s2);
    { dim3 g(blocks(E, TB), 3); count_deg_kernel<<<g, TB, 0, s2>>>(ei, degi, E, M, 0); }
    rsqrt_kernel<<<blocks((long)6 * M, TB), TB, 0, s2>>>(degi, degf, 6 * M);
    { dim3 g(nblk_scan, 3); scanA<<<g, 256, 0, s2>>>(degi, off, bsum, M, 0); }
    scanB<<<3, MAXBLK, 0, s2>>>(bsum, nblk_scan, 0);
    { dim3 g(blocks(M, TB), 3); scanC<<<g, TB, 0, s2>>>(off, cnt, bsum, M, 0); }
    { dim3 g(blocks(E, TB), 3); fill_adj_kernel<<<g, TB, 0, s2>>>(ei, cnt, adj, E, M, 0); }
    cudaEventRecord(evCsr1, s2);
    { dim3 g(blocks(E, TB), 3); count_deg_kernel<<<g, TB, 0, s2>>>(ei, degi, E, M, 3); }
    rsqrt_kernel<<<blocks((long)6 * M, TB), TB, 0, s2>>>(degi + (size_t)6 * M, degf + (size_t)6 * M, 6 * M);
    cudaEventRecord(evDeg2, s2);
    { dim3 g(nblk_scan, 3); scanA<<<g, 256, 0, s2>>>(degi, off, bsum, M, 3); }
    scanB<<<3, MAXBLK, 0, s2>>>(bsum, nblk_scan, 3);
    { dim3 g(blocks(M, TB), 3); scanC<<<g, TB, 0, s2>>>(off, cnt, bsum, M, 3); }
    { dim3 g(blocks(E, TB), 3); fill_adj_kernel<<<g, TB, 0, s2>>>(ei, cnt, adj, E, M, 3); }
    cudaEventRecord(evCsr2, s2);

    // ---- join: gatherL1 -> layer-2 GEMM -> gatherL2 ----------------------------
    cudaStreamWaitEvent(0, evCsr1, 0);
    gatherL1<<<gw, TB>>>(z3, ahi, alo, off, degi, adj, degf, b1, M, E);

    cudaStreamWaitEvent(0, evDeg2, 0);
    gemm_fused<64, true><<<gemm_grid, 256, SMEM_L2>>>(
        ahi, alo, w2hi, w2lo, degf + (size_t)6 * M, z3, M);

    cudaStreamWaitEvent(0, evCsr2, 0);
    gatherL2<<<gw, TB>>>(z3, out, off, degi, adj, degf, b2, M, E);

    cudaStreamDestroy(s2);
    cudaEventDestroy(evFork);
    cudaEventDestroy(evCsr1);
    cudaEventDestroy(evDeg2);
    cudaEventDestroy(evCsr2);
}

// round 14
// speedup vs baseline: 1.3953x; 1.0341x over previous
#include <cuda_runtime.h>
#include <cuda_bf16.h>
#include <cuda_fp16.h>
#include <mma.h>
#include <cstdint>

using namespace nvcuda;

// ---------------- problem constants ------------------------------------------
#define NMAX   100000
#define EMAX   1600000
#define DIN    128
#define DH     128
#define DOUT   64
#define NREL   3
#define NPAIR  6
#define SCAN_CHUNK 1024
#define MAXBLK 128

// ---------------- scratch (__device__ globals; no allocation allowed) --------
__device__ __align__(128) __half g_z3[(size_t)NMAX * (NREL * DIN)];
__device__ __align__(128) __nv_bfloat16 g_ahi[(size_t)NMAX * DIN];
__device__ __align__(128) __nv_bfloat16 g_alo[(size_t)NMAX * DIN];
__device__ __align__(128) __nv_bfloat16 g_w1hi[NREL * DIN * DH], g_w1lo[NREL * DIN * DH];
__device__ __align__(128) __nv_bfloat16 g_w2hi[NREL * DH * DOUT], g_w2lo[NREL * DH * DOUT];
__device__ int   g_degi[12 * NMAX];
__device__ float g_degf[12 * NMAX];
__device__ int   g_off [NPAIR * NMAX];
__device__ int   g_cnt [NPAIR * NMAX];
__device__ int   g_adj [(size_t)NPAIR * EMAX];
__device__ int   g_bsum[NPAIR * MAXBLK];

// ---------------- cp.async helpers -------------------------------------------
__device__ __forceinline__ void cpa16(void* smem, const void* g, bool valid) {
    uint32_t s = (uint32_t)__cvta_generic_to_shared(smem);
    int sz = valid ? 16 : 0;
    asm volatile("cp.async.cg.shared.global [%0], [%1], 16, %2;\n"
                 :: "r"(s), "l"(g), "r"(sz));
}
__device__ __forceinline__ void cpa_commit() {
    asm volatile("cp.async.commit_group;\n" ::: "memory");
}
__device__ __forceinline__ void cpa_wait0() {
    asm volatile("cp.async.wait_group 0;\n" ::: "memory");
}

// ---------------- fp32 -> (bf16 hi, bf16 lo) split ---------------------------
__global__ void split_kernel(const float* __restrict__ src,
                             __nv_bfloat16* __restrict__ hi,
                             __nv_bfloat16* __restrict__ lo, int n) {
    int i = blockIdx.x * blockDim.x + threadIdx.x;
    if (i >= n) return;
    float v = __ldg(src + i);
    __nv_bfloat16 h = __float2bfloat16(v);
    hi[i] = h;
    lo[i] = __float2bfloat16(v - __bfloat162float(h));
}

// ---------------- degree counting (pbase selects pair range) ------------------
__global__ void count_deg_kernel(const int* __restrict__ ei, int* __restrict__ degi,
                                 int E, int M, int pbase) {
    int p = pbase + blockIdx.y;
    int e = blockIdx.x * blockDim.x + threadIdx.x;
    if (e >= E) return;
    int s = __ldg(ei + (size_t)(p * 2 + 0) * E + e);
    int d = __ldg(ei + (size_t)(p * 2 + 1) * E + e);
    atomicAdd(degi + (size_t)(p * 2 + 0) * M + s, 1);
    atomicAdd(degi + (size_t)(p * 2 + 1) * M + d, 1);
}

__global__ void rsqrt_kernel(const int* __restrict__ degi, float* __restrict__ degf, int n) {
    int i = blockIdx.x * blockDim.x + threadIdx.x;
    if (i < n) degf[i] = rsqrtf((float)max(degi[i], 1));
}

// ---------------- exclusive scan -> CSR offsets -------------------------------
__global__ __launch_bounds__(256)
void scanA(const int* __restrict__ degi, int* __restrict__ off,
           int* __restrict__ bsum, int M, int pbase) {
    int p = pbase + blockIdx.y;
    const int* deg = degi + (size_t)(p * 2 + 1) * M;
    int* o = off + (size_t)p * M;
    int base = blockIdx.x * SCAN_CHUNK;
    int tid = threadIdx.x;

    int v[4];
    int t = 0;
    #pragma unroll
    for (int k = 0; k < 4; k++) {
        int idx = base + tid * 4 + k;
        v[k] = (idx < M) ? deg[idx] : 0;
        t += v[k];
    }
    __shared__ int sm[256];
    sm[tid] = t;
    __syncthreads();
    #pragma unroll
    for (int ofs = 1; ofs < 256; ofs <<= 1) {
        int u = (tid >= ofs) ? sm[tid - ofs] : 0;
        __syncthreads();
        sm[tid] += u;
        __syncthreads();
    }
    int run = sm[tid] - t;
    #pragma unroll
    for (int k = 0; k < 4; k++) {
        int idx = base + tid * 4 + k;
        if (idx < M) o[idx] = run;
        run += v[k];
    }
    if (tid == 255) bsum[p * MAXBLK + blockIdx.x] = sm[255];
}

__global__ __launch_bounds__(MAXBLK)
void scanB(int* __restrict__ bsum, int nblk, int pbase) {
    int p = pbase + blockIdx.x;
    int tid = threadIdx.x;
    int* b = bsum + p * MAXBLK;
    int t = (tid < nblk) ? b[tid] : 0;
    __shared__ int sm[MAXBLK];
    sm[tid] = t;
    __syncthreads();
    #pragma unroll
    for (int ofs = 1; ofs < MAXBLK; ofs <<= 1) {
        int u = (tid >= ofs) ? sm[tid - ofs] : 0;
        __syncthreads();
        sm[tid] += u;
        __syncthreads();
    }
    if (tid < nblk) b[tid] = sm[tid] - t;
}

__global__ void scanC(int* __restrict__ off, int* __restrict__ cnt,
                      const int* __restrict__ bsum, int M, int pbase) {
    int p = pbase + blockIdx.y;
    int i = blockIdx.x * blockDim.x + threadIdx.x;
    if (i < M) {
        int v = off[(size_t)p * M + i] + bsum[p * MAXBLK + (i >> 10)];
        off[(size_t)p * M + i] = v;
        cnt[(size_t)p * M + i] = v;
    }
}

__global__ void fill_adj_kernel(const int* __restrict__ ei,
                                int* __restrict__ cnt, int* __restrict__ adj,
                                int E, int M, int pbase) {
    int p = pbase + blockIdx.y;
    int e = blockIdx.x * blockDim.x + threadIdx.x;
    if (e >= E) return;
    int s = __ldg(ei + (size_t)(p * 2 + 0) * E + e);
    int d = __ldg(ei + (size_t)(p * 2 + 1) * E + e);
    int pos = atomicAdd(cnt + (size_t)p * M + d, 1);
    adj[(size_t)p * E + pos] = s;
}

// ---------------- relation-fused, double-buffered bf16-split GEMM ------------
// C[M, NREL*BN] : for each r, C[:, r*BN:(r+1)*BN] = scale_r * (A @ B_r)
// BM=128. Warp tile 32x32 (MT=NT=2). THREADS=512 -> 4x4 warp grid (BN=128);
// THREADS=256 -> 4x2 warp grid (BN=64, 2 CTAs/SM).
#define A_ST 136                 // A smem stride (bf16 elems)
#define EPI_ST 36                // epilogue stride (fp32), 32 cols + pad

template<int BN, int THREADS, bool SCALE>
__global__ __launch_bounds__(THREADS)
void gemm_fused(const __nv_bfloat16* __restrict__ Ahi,
                const __nv_bfloat16* __restrict__ Alo,
                const __nv_bfloat16* __restrict__ Bhi,   // [NREL][128][BN]
                const __nv_bfloat16* __restrict__ Blo,
                const float* __restrict__ rsbase,        // rs_r = rsbase + r*2*M
                __half* __restrict__ C, int M) {
    constexpr int LDC = NREL * BN;
    constexpr int WARPS = THREADS / 32;
    constexpr int WC = BN / 32;               // warp cols
    constexpr int WR = WARPS / WC;            // warp rows (=4)
    static_assert(WR * 32 == 128, "warp rows must tile BM");
    constexpr int BST = BN + 8;
    constexpr int KCH = 4;                    // 128 / 32
    constexpr int TOT = NREL * KCH;
    constexpr int BXF = 32 * BN / 8;          // 16B xfers per (hi|lo) B chunk

    extern __shared__ __align__(16) char dsm[];
    __nv_bfloat16* sAhi = reinterpret_cast<__nv_bfloat16*>(dsm);
    __nv_bfloat16* sAlo = sAhi + 128 * A_ST;
    __nv_bfloat16* sB   = sAlo + 128 * A_ST;  // [2 stages][hi,lo][32*BST]
    float* epiBase = reinterpret_cast<float*>(sB + 2 * 2 * 32 * BST);

    const int tid  = threadIdx.x;
    const int w    = tid >> 5;
    const int lane = tid & 31;
    const int warp_row = w % WR;
    const int warp_col = w / WR;
    const int m_off = warp_row * 32;
    const int n_off = warp_col * 32;
    const int row0 = blockIdx.x * 128;

    // ---- A: one-time cp.async load (hi + lo), zero-fill rows >= M ----------
    #pragma unroll
    for (int i = 0; i < 2048 / THREADS; i++) {
        int slot = tid + i * THREADS;
        int r = slot >> 4;
        int c = (slot & 15) * 8;
        int gr = row0 + r;
        bool valid = gr < M;
        const __nv_bfloat16* gh = Ahi + (size_t)gr * 128 + c;
        const __nv_bfloat16* gl = Alo + (size_t)gr * 128 + c;
        cpa16(sAhi + r * A_ST + c, valid ? gh : (const void*)Ahi, valid);
        cpa16(sAlo + r * A_ST + c, valid ? gl : (const void*)Alo, valid);
    }

    auto loadB = [&](int it, int st) {
        int rel = it / KCH;
        int kc = (it % KCH) * 32;
        __nv_bfloat16* dh = sB + st * 2 * 32 * BST;
        __nv_bfloat16* dl = dh + 32 * BST;
        const __nv_bfloat16* gh = Bhi + (size_t)rel * 128 * BN;
        const __nv_bfloat16* gl = Blo + (size_t)rel * 128 * BN;
        #pragma unroll
        for (int i = 0; i < BXF / THREADS; i++) {
            int slot = tid + i * THREADS;
            int r = slot / (BN / 8);
            int c = (slot % (BN / 8)) * 8;
            cpa16(dh + r * BST + c, gh + (size_t)(kc + r) * BN + c, true);
            cpa16(dl + r * BST + c, gl + (size_t)(kc + r) * BN + c, true);
        }
    };
    loadB(0, 0);
    cpa_commit();

    wmma::fragment<wmma::accumulator, 16, 16, 16, float> acc[2][2];
    #pragma unroll
    for (int mt = 0; mt < 2; mt++)
        #pragma unroll
        for (int n = 0; n < 2; n++) wmma::fill_fragment(acc[mt][n], 0.0f);

    for (int it = 0; it < TOT; it++) {
        cpa_wait0();
        __syncthreads();
        if (it + 1 < TOT) { loadB(it + 1, (it + 1) & 1); cpa_commit(); }

        const int cur = it & 1;
        const int kc = (it % KCH) * 32;
        const __nv_bfloat16* bh = sB + cur * 2 * 32 * BST;
        const __nv_bfloat16* bl = bh + 32 * BST;

        #pragma unroll
        for (int ks = 0; ks < 32; ks += 16) {
            wmma::fragment<wmma::matrix_a, 16, 16, 16, __nv_bfloat16, wmma::row_major> fahi[2], falo[2];
            wmma::fragment<wmma::matrix_b, 16, 16, 16, __nv_bfloat16, wmma::row_major> fbhi[2], fblo[2];
            #pragma unroll
            for (int mt = 0; mt < 2; mt++) {
                wmma::load_matrix_sync(fahi[mt], sAhi + (m_off + mt * 16) * A_ST + kc + ks, A_ST);
                wmma::load_matrix_sync(falo[mt], sAlo + (m_off + mt * 16) * A_ST + kc + ks, A_ST);
            }
            #pragma unroll
            for (int n = 0; n < 2; n++) {
                wmma::load_matrix_sync(fbhi[n], bh + ks * BST + n_off + n * 16, BST);
                wmma::load_matrix_sync(fblo[n], bl + ks * BST + n_off + n * 16, BST);
            }
            #pragma unroll
            for (int mt = 0; mt < 2; mt++)
                #pragma unroll
                for (int n = 0; n < 2; n++) {
                    wmma::mma_sync(acc[mt][n], fahi[mt], fbhi[n], acc[mt][n]);
                    wmma::mma_sync(acc[mt][n], fahi[mt], fblo[n], acc[mt][n]);
                    wmma::mma_sync(acc[mt][n], falo[mt], fbhi[n], acc[mt][n]);
                }
        }

        if ((it % KCH) == KCH - 1) {
            int rel = it / KCH;
            const float* rs = rsbase + (size_t)rel * 2 * M;
            float* epi = epiBase + w * 16 * EPI_ST;
            #pragma unroll
            for (int mt = 0; mt < 2; mt++) {
                #pragma unroll
                for (int n = 0; n < 2; n++)
                    wmma::store_matrix_sync(epi + n * 16, acc[mt][n], EPI_ST, wmma::mem_row_major);
                __syncwarp();
                int gr0 = row0 + m_off + mt * 16;
                #pragma unroll
                for (int itc = 0; itc < 4; itc++) {
                    int idx = itc * 32 + lane;        // 16 rows x 8 float4
                    int r = idx >> 3;
                    int c4 = (idx & 7) * 4;
                    int gr = gr0 + r;
                    if (gr < M) {
                        float s = SCALE ? __ldg(rs + gr) : 1.0f;
                        float4 v = *reinterpret_cast<float4*>(epi + r * EPI_ST + c4);
                        __half2 p0 = __floats2half2_rn(v.x * s, v.y * s);
                        __half2 p1 = __floats2half2_rn(v.z * s, v.w * s);
                        uint2 o;
                        o.x = *reinterpret_cast<uint32_t*>(&p0);
                        o.y = *reinterpret_cast<uint32_t*>(&p1);
                        *reinterpret_cast<uint2*>(C + (size_t)gr * LDC + rel * BN + n_off + c4) = o;
                    }
                }
                __syncwarp();
            }
            #pragma unroll
            for (int mt = 0; mt < 2; mt++)
                #pragma unroll
                for (int n = 0; n < 2; n++) wmma::fill_fragment(acc[mt][n], 0.0f);
        }
    }
}

// ---------------- fused 3-relation gathers ------------------------------------
__global__ __launch_bounds__(256)
void gatherL1(const __half* __restrict__ z3,
              __nv_bfloat16* __restrict__ ahi, __nv_bfloat16* __restrict__ alo,
              const int* __restrict__ off, const int* __restrict__ degi,
              const int* __restrict__ adj, const float* __restrict__ degf,
              const float* __restrict__ b1, int M, int E) {
    int w = (blockIdx.x * blockDim.x + threadIdx.x) >> 5;
    if (w >= M) return;
    int lane = threadIdx.x & 31;
    float4 tot = make_float4(0.f, 0.f, 0.f, 0.f);

    #pragma unroll
    for (int r = 0; r < NREL; r++) {
        const int*   offp  = off  + (size_t)r * M;
        const int*   degp  = degi + (size_t)(r * 2 + 1) * M;
        const int*   adjp  = adj  + (size_t)r * E;
        const float* rsout = degf + (size_t)(r * 2 + 0) * M;
        const float* rsin  = degf + (size_t)(r * 2 + 1) * M;
        int st = __ldg(offp + w);
        int len = __ldg(degp + w);
        float4 acc = make_float4(0.f, 0.f, 0.f, 0.f);
        const __half* zr = z3 + (size_t)r * 128;
        int j = 0;
        for (; j + 1 < len; j += 2) {
            int s0 = __ldg(adjp + st + j);
            int s1 = __ldg(adjp + st + j + 1);
            float c0 = __ldg(rsout + s0);
            float c1 = __ldg(rsout + s1);
            uint2 r0 = __ldg(reinterpret_cast<const uint2*>(zr + (size_t)s0 * 384 + lane * 4));
            uint2 r1 = __ldg(reinterpret_cast<const uint2*>(zr + (size_t)s1 * 384 + lane * 4));
            float2 a = __half22float2(*reinterpret_cast<__half2*>(&r0.x));
            float2 b = __half22float2(*reinterpret_cast<__half2*>(&r0.y));
            float2 c2 = __half22float2(*reinterpret_cast<__half2*>(&r1.x));
            float2 d2 = __half22float2(*reinterpret_cast<__half2*>(&r1.y));
            acc.x += c0 * a.x + c1 * c2.x; acc.y += c0 * a.y + c1 * c2.y;
            acc.z += c0 * b.x + c1 * d2.x; acc.w += c0 * b.y + c1 * d2.y;
        }
        if (j < len) {
            int s0 = __ldg(adjp + st + j);
            float c0 = __ldg(rsout + s0);
            uint2 r0 = __ldg(reinterpret_cast<const uint2*>(zr + (size_t)s0 * 384 + lane * 4));
            float2 a = __half22float2(*reinterpret_cast<__half2*>(&r0.x));
            float2 b = __half22float2(*reinterpret_cast<__half2*>(&r0.y));
            acc.x += c0 * a.x; acc.y += c0 * a.y;
            acc.z += c0 * b.x; acc.w += c0 * b.y;
        }
        float ci = __ldg(rsin + w);
        tot.x += ci * acc.x; tot.y += ci * acc.y;
        tot.z += ci * acc.z; tot.w += ci * acc.w;
    }

    int col = lane * 4;
    tot.x = fmaxf(tot.x + __ldg(b1 + col + 0) + __ldg(b1 + 128 + col + 0) + __ldg(b1 + 256 + col + 0), 0.f);
    tot.y = fmaxf(tot.y + __ldg(b1 + col + 1) + __ldg(b1 + 128 + col + 1) + __ldg(b1 + 256 + col + 1), 0.f);
    tot.z = fmaxf(tot.z + __ldg(b1 + col + 2) + __ldg(b1 + 128 + col + 2) + __ldg(b1 + 256 + col + 2), 0.f);
    tot.w = fmaxf(tot.w + __ldg(b1 + col + 3) + __ldg(b1 + 128 + col + 3) + __ldg(b1 + 256 + col + 3), 0.f);

    __nv_bfloat16 hx = __float2bfloat16(tot.x), hy = __float2bfloat16(tot.y);
    __nv_bfloat16 hz = __float2bfloat16(tot.z), hw = __float2bfloat16(tot.w);
    __nv_bfloat16 lx = __float2bfloat16(tot.x - __bfloat162float(hx));
    __nv_bfloat16 ly = __float2bfloat16(tot.y - __bfloat162float(hy));
    __nv_bfloat16 lz = __float2bfloat16(tot.z - __bfloat162float(hz));
    __nv_bfloat16 lw = __float2bfloat16(tot.w - __bfloat162float(hw));
    __nv_bfloat162 h0 = __nv_bfloat162(hx, hy), h1 = __nv_bfloat162(hz, hw);
    __nv_bfloat162 l0 = __nv_bfloat162(lx, ly), l1 = __nv_bfloat162(lz, lw);
    uint2 oh, ol;
    oh.x = *reinterpret_cast<uint32_t*>(&h0); oh.y = *reinterpret_cast<uint32_t*>(&h1);
    ol.x = *reinterpret_cast<uint32_t*>(&l0); ol.y = *reinterpret_cast<uint32_t*>(&l1);
    *reinterpret_cast<uint2*>(ahi + (size_t)w * 128 + col) = oh;
    *reinterpret_cast<uint2*>(alo + (size_t)w * 128 + col) = ol;
}

__global__ __launch_bounds__(256)
void gatherL2(const __half* __restrict__ z3, float* __restrict__ out,
              const int* __restrict__ off, const int* __restrict__ degi,
              const int* __restrict__ adj, const float* __restrict__ degf,
              const float* __restrict__ b2, int M, int E) {
    int w = (blockIdx.x * blockDim.x + threadIdx.x) >> 5;
    if (w >= M) return;
    int lane = threadIdx.x & 31;
    float2 tot = make_float2(0.f, 0.f);

    #pragma unroll
    for (int r = 0; r < NREL; r++) {
        int p = NREL + r;
        const int*   offp  = off  + (size_t)p * M;
        const int*   degp  = degi + (size_t)(p * 2 + 1) * M;
        const int*   adjp  = adj  + (size_t)p * E;
        const float* rsin  = degf + (size_t)(p * 2 + 1) * M;
        int st = __ldg(offp + w);
        int len = __ldg(degp + w);
        float2 acc = make_float2(0.f, 0.f);
        const __half* zr = z3 + (size_t)r * 64;
        int j = 0;
        for (; j + 1 < len; j += 2) {
            int s0 = __ldg(adjp + st + j);
            int s1 = __ldg(adjp + st + j + 1);
            uint32_t r0 = __ldg(reinterpret_cast<const uint32_t*>(zr + (size_t)s0 * 192 + lane * 2));
            uint32_t r1 = __ldg(reinterpret_cast<const uint32_t*>(zr + (size_t)s1 * 192 + lane * 2));
            float2 a = __half22float2(*reinterpret_cast<__half2*>(&r0));
            float2 b = __half22float2(*reinterpret_cast<__half2*>(&r1));
            acc.x += a.x + b.x; acc.y += a.y + b.y;
        }
        if (j < len) {
            int s0 = __ldg(adjp + st + j);
            uint32_t r0 = __ldg(reinterpret_cast<const uint32_t*>(zr + (size_t)s0 * 192 + lane * 2));
            float2 a = __half22float2(*reinterpret_cast<__half2*>(&r0));
            acc.x += a.x; acc.y += a.y;
        }
        float ci = __ldg(rsin + w);
        tot.x += ci * acc.x; tot.y += ci * acc.y;
    }

    int col = lane * 2;
    tot.x += __ldg(b2 + col + 0) + __ldg(b2 + 64 + col + 0) + __ldg(b2 + 128 + col + 0);
    tot.y += __ldg(b2 + col + 1) + __ldg(b2 + 64 + col + 1) + __ldg(b2 + 128 + col + 1);
    *reinterpret_cast<float2*>(out + (size_t)w * 64 + col) = tot;
}

// ---------------- orchestration ----------------------------------------------
extern "C" void kernel_launch(void* const* d_in, const int* in_sizes, int n_in,
                              void* d_out, int out_size) {
    const float* x  = (const float*)d_in[0];
    const float* W1 = (const float*)d_in[1];
    const float* b1 = (const float*)d_in[2];
    const float* W2 = (const float*)d_in[3];
    const float* b2 = (const float*)d_in[4];
    const int*   ei = (const int*)d_in[5];
    float* out = (float*)d_out;

    const int M = in_sizes[0] / DIN;
    const int E = in_sizes[5] / (2 * NREL * 2);

    float* degf;
    __half* z3;
    __nv_bfloat16 *ahi, *alo, *w1hi, *w1lo, *w2hi, *w2lo;
    int *degi, *off, *cnt, *adj, *bsum;
    cudaGetSymbolAddress((void**)&z3,   g_z3);
    cudaGetSymbolAddress((void**)&ahi,  g_ahi);
    cudaGetSymbolAddress((void**)&alo,  g_alo);
    cudaGetSymbolAddress((void**)&w1hi, g_w1hi);
    cudaGetSymbolAddress((void**)&w1lo, g_w1lo);
    cudaGetSymbolAddress((void**)&w2hi, g_w2hi);
    cudaGetSymbolAddress((void**)&w2lo, g_w2lo);
    cudaGetSymbolAddress((void**)&degf, g_degf);
    cudaGetSymbolAddress((void**)&degi, g_degi);
    cudaGetSymbolAddress((void**)&off,  g_off);
    cudaGetSymbolAddress((void**)&cnt,  g_cnt);
    cudaGetSymbolAddress((void**)&adj,  g_adj);
    cudaGetSymbolAddress((void**)&bsum, g_bsum);

    const int TB = 256;
    auto blocks = [](long n, int tb) { return (int)((n + tb - 1) / tb); };
    const int nblk_scan = (M + SCAN_CHUNK - 1) / SCAN_CHUNK;
    const int gemm_grid = (M + 127) / 128;
    const int gw = blocks((long)M * 32, TB);

    // dynamic smem: A(69632) + B(2*2*32*BST*2) + epi(WARPS*16*EPI_ST*4)
    const int SMEM_L1 = 128 * A_ST * 2 * 2 + 2 * 2 * 32 * (128 + 8) * 2 + 16 * 16 * EPI_ST * 4;
    const int SMEM_L2 = 128 * A_ST * 2 * 2 + 2 * 2 * 32 * (64 + 8) * 2 + 8 * 16 * EPI_ST * 4;
    cudaFuncSetAttribute(gemm_fused<128, 512, false>,
                         cudaFuncAttributeMaxDynamicSharedMemorySize, SMEM_L1);
    cudaFuncSetAttribute(gemm_fused<64, 256, true>,
                         cudaFuncAttributeMaxDynamicSharedMemorySize, SMEM_L2);

    // ---- fork side stream for CSR build ---------------------------------------
    cudaStream_t s2;
    cudaStreamCreateWithFlags(&s2, cudaStreamNonBlocking);
    cudaEvent_t evFork, evCsr1, evDeg2, evCsr2;
    cudaEventCreateWithFlags(&evFork, cudaEventDisableTiming);
    cudaEventCreateWithFlags(&evCsr1, cudaEventDisableTiming);
    cudaEventCreateWithFlags(&evDeg2, cudaEventDisableTiming);
    cudaEventCreateWithFlags(&evCsr2, cudaEventDisableTiming);
    cudaEventRecord(evFork, 0);
    cudaStreamWaitEvent(s2, evFork, 0);

    // ---- main: splits + fused layer-1 GEMM (degree-independent) ---------------
    split_kernel<<<blocks((long)M * DIN, TB), TB>>>(x, ahi, alo, M * DIN);
    split_kernel<<<blocks(NREL * DIN * DH, TB), TB>>>(W1, w1hi, w1lo, NREL * DIN * DH);
    split_kernel<<<blocks(NREL * DH * DOUT, TB), TB>>>(W2, w2hi, w2lo, NREL * DH * DOUT);
    gemm_fused<128, 512, false><<<gemm_grid, 512, SMEM_L1>>>(
        ahi, alo, w1hi, w1lo, nullptr, z3, M);

    // ---- side: layer-1 CSR, then layer-2 CSR ----------------------------------
    cudaMemsetAsync(degi, 0, (size_t)12 * M * sizeof(int), s2);
    { dim3 g(blocks(E, TB), 3); count_deg_kernel<<<g, TB, 0, s2>>>(ei, degi, E, M, 0); }
    rsqrt_kernel<<<blocks((long)6 * M, TB), TB, 0, s2>>>(degi, degf, 6 * M);
    { dim3 g(nblk_scan, 3); scanA<<<g, 256, 0, s2>>>(degi, off, bsum, M, 0); }
    scanB<<<3, MAXBLK, 0, s2>>>(bsum, nblk_scan, 0);
    { dim3 g(blocks(M, TB), 3); scanC<<<g, TB, 0, s2>>>(off, cnt, bsum, M, 0); }
    { dim3 g(blocks(E, TB), 3); fill_adj_kernel<<<g, TB, 0, s2>>>(ei, cnt, adj, E, M, 0); }
    cudaEventRecord(evCsr1, s2);
    { dim3 g(blocks(E, TB), 3); count_deg_kernel<<<g, TB, 0, s2>>>(ei, degi, E, M, 3); }
    rsqrt_kernel<<<blocks((long)6 * M, TB), TB, 0, s2>>>(degi + (size_t)6 * M, degf + (size_t)6 * M, 6 * M);
    cudaEventRecord(evDeg2, s2);
    { dim3 g(nblk_scan, 3); scanA<<<g, 256, 0, s2>>>(degi, off, bsum, M, 3); }
    scanB<<<3, MAXBLK, 0, s2>>>(bsum, nblk_scan, 3);
    { dim3 g(blocks(M, TB), 3); scanC<<<g, TB, 0, s2>>>(off, cnt, bsum, M, 3); }
    { dim3 g(blocks(E, TB), 3); fill_adj_kernel<<<g, TB, 0, s2>>>(ei, cnt, adj, E, M, 3); }
    cudaEventRecord(evCsr2, s2);

    // ---- join: gatherL1 -> layer-2 GEMM -> gatherL2 ----------------------------
    cudaStreamWaitEvent(0, evCsr1, 0);
    gatherL1<<<gw, TB>>>(z3, ahi, alo, off, degi, adj, degf, b1, M, E);

    cudaStreamWaitEvent(0, evDeg2, 0);
    gemm_fused<64, 256, true><<<gemm_grid, 256, SMEM_L2>>>(
        ahi, alo, w2hi, w2lo, degf + (size_t)6 * M, z3, M);

    cudaStreamWaitEvent(0, evCsr2, 0);
    gatherL2<<<gw, TB>>>(z3, out, off, degi, adj, degf, b2, M, E);

    cudaStreamDestroy(s2);
    cudaEventDestroy(evFork);
    cudaEventDestroy(evCsr1);
    cudaEventDestroy(evDeg2);
    cudaEventDestroy(evCsr2);
}

// round 15
// speedup vs baseline: 1.5175x; 1.0876x over previous
#include <cuda_runtime.h>
#include <cuda_bf16.h>
#include <cuda_fp16.h>
#include <cstdint>

// ---------------- problem constants ------------------------------------------
#define NMAX   100000
#define EMAX   1600000
#define DIN    128
#define DH     128
#define DOUT   64
#define NREL   3
#define NPAIR  6
#define SCAN_CHUNK 1024
#define MAXBLK 128

// ---------------- scratch (__device__ globals; no allocation allowed) --------
__device__ __align__(128) __half g_z3[(size_t)NMAX * (NREL * DIN)];
__device__ __align__(128) __nv_bfloat16 g_ahi[(size_t)NMAX * DIN];
__device__ __align__(128) __nv_bfloat16 g_alo[(size_t)NMAX * DIN];
__device__ __align__(128) __nv_bfloat16 g_w1hi[NREL * DIN * DH], g_w1lo[NREL * DIN * DH];
__device__ __align__(128) __nv_bfloat16 g_w2hi[NREL * DH * DOUT], g_w2lo[NREL * DH * DOUT];
__device__ int   g_degi[12 * NMAX];
__device__ float g_degf[12 * NMAX];
__device__ int   g_off [NPAIR * NMAX];
__device__ int   g_cnt [NPAIR * NMAX];
__device__ int   g_adj [(size_t)NPAIR * EMAX];
__device__ int   g_bsum[NPAIR * MAXBLK];

// ---------------- cp.async / mma helpers --------------------------------------
__device__ __forceinline__ void cpa16(void* smem, const void* g, bool valid) {
    uint32_t s = (uint32_t)__cvta_generic_to_shared(smem);
    int sz = valid ? 16 : 0;
    asm volatile("cp.async.cg.shared.global [%0], [%1], 16, %2;\n"
                 :: "r"(s), "l"(g), "r"(sz));
}
__device__ __forceinline__ void cpa_commit() {
    asm volatile("cp.async.commit_group;\n" ::: "memory");
}
__device__ __forceinline__ void cpa_wait0() {
    asm volatile("cp.async.wait_group 0;\n" ::: "memory");
}
__device__ __forceinline__ void ldsm_x4(uint32_t* r, uint32_t addr) {
    asm volatile("ldmatrix.sync.aligned.m8n8.x4.shared.b16 {%0,%1,%2,%3}, [%4];"
                 : "=r"(r[0]), "=r"(r[1]), "=r"(r[2]), "=r"(r[3]) : "r"(addr));
}
__device__ __forceinline__ void ldsm_x4t(uint32_t* r, uint32_t addr) {
    asm volatile("ldmatrix.sync.aligned.m8n8.x4.trans.shared.b16 {%0,%1,%2,%3}, [%4];"
                 : "=r"(r[0]), "=r"(r[1]), "=r"(r[2]), "=r"(r[3]) : "r"(addr));
}
__device__ __forceinline__ void mma16816(float* d, const uint32_t* a, const uint32_t* b) {
    asm volatile("mma.sync.aligned.m16n8k16.row.col.f32.bf16.bf16.f32 "
                 "{%0,%1,%2,%3},{%4,%5,%6,%7},{%8,%9},{%0,%1,%2,%3};"
                 : "+f"(d[0]), "+f"(d[1]), "+f"(d[2]), "+f"(d[3])
                 : "r"(a[0]), "r"(a[1]), "r"(a[2]), "r"(a[3]), "r"(b[0]), "r"(b[1]));
}

// ---------------- fp32 -> (bf16 hi, bf16 lo) split ---------------------------
__global__ void split_kernel(const float* __restrict__ src,
                             __nv_bfloat16* __restrict__ hi,
                             __nv_bfloat16* __restrict__ lo, int n) {
    int i = blockIdx.x * blockDim.x + threadIdx.x;
    if (i >= n) return;
    float v = __ldg(src + i);
    __nv_bfloat16 h = __float2bfloat16(v);
    hi[i] = h;
    lo[i] = __float2bfloat16(v - __bfloat162float(h));
}

// ---------------- degree counting ---------------------------------------------
__global__ void count_deg_kernel(const int* __restrict__ ei, int* __restrict__ degi,
                                 int E, int M, int pbase) {
    int p = pbase + blockIdx.y;
    int e = blockIdx.x * blockDim.x + threadIdx.x;
    if (e >= E) return;
    int s = __ldg(ei + (size_t)(p * 2 + 0) * E + e);
    int d = __ldg(ei + (size_t)(p * 2 + 1) * E + e);
    atomicAdd(degi + (size_t)(p * 2 + 0) * M + s, 1);
    atomicAdd(degi + (size_t)(p * 2 + 1) * M + d, 1);
}

__global__ void rsqrt_kernel(const int* __restrict__ degi, float* __restrict__ degf, int n) {
    int i = blockIdx.x * blockDim.x + threadIdx.x;
    if (i < n) degf[i] = rsqrtf((float)max(degi[i], 1));
}

// ---------------- exclusive scan -> CSR offsets -------------------------------
__global__ __launch_bounds__(256)
void scanA(const int* __restrict__ degi, int* __restrict__ off,
           int* __restrict__ bsum, int M, int pbase) {
    int p = pbase + blockIdx.y;
    const int* deg = degi + (size_t)(p * 2 + 1) * M;
    int* o = off + (size_t)p * M;
    int base = blockIdx.x * SCAN_CHUNK;
    int tid = threadIdx.x;

    int v[4];
    int t = 0;
    #pragma unroll
    for (int k = 0; k < 4; k++) {
        int idx = base + tid * 4 + k;
        v[k] = (idx < M) ? deg[idx] : 0;
        t += v[k];
    }
    __shared__ int sm[256];
    sm[tid] = t;
    __syncthreads();
    #pragma unroll
    for (int ofs = 1; ofs < 256; ofs <<= 1) {
        int u = (tid >= ofs) ? sm[tid - ofs] : 0;
        __syncthreads();
        sm[tid] += u;
        __syncthreads();
    }
    int run = sm[tid] - t;
    #pragma unroll
    for (int k = 0; k < 4; k++) {
        int idx = base + tid * 4 + k;
        if (idx < M) o[idx] = run;
        run += v[k];
    }
    if (tid == 255) bsum[p * MAXBLK + blockIdx.x] = sm[255];
}

__global__ __launch_bounds__(MAXBLK)
void scanB(int* __restrict__ bsum, int nblk, int pbase) {
    int p = pbase + blockIdx.x;
    int tid = threadIdx.x;
    int* b = bsum + p * MAXBLK;
    int t = (tid < nblk) ? b[tid] : 0;
    __shared__ int sm[MAXBLK];
    sm[tid] = t;
    __syncthreads();
    #pragma unroll
    for (int ofs = 1; ofs < MAXBLK; ofs <<= 1) {
        int u = (tid >= ofs) ? sm[tid - ofs] : 0;
        __syncthreads();
        sm[tid] += u;
        __syncthreads();
    }
    if (tid < nblk) b[tid] = sm[tid] - t;
}

__global__ void scanC(int* __restrict__ off, int* __restrict__ cnt,
                      const int* __restrict__ bsum, int M, int pbase) {
    int p = pbase + blockIdx.y;
    int i = blockIdx.x * blockDim.x + threadIdx.x;
    if (i < M) {
        int v = off[(size_t)p * M + i] + bsum[p * MAXBLK + (i >> 10)];
        off[(size_t)p * M + i] = v;
        cnt[(size_t)p * M + i] = v;
    }
}

__global__ void fill_adj_kernel(const int* __restrict__ ei,
                                int* __restrict__ cnt, int* __restrict__ adj,
                                int E, int M, int pbase) {
    int p = pbase + blockIdx.y;
    int e = blockIdx.x * blockDim.x + threadIdx.x;
    if (e >= E) return;
    int s = __ldg(ei + (size_t)(p * 2 + 0) * E + e);
    int d = __ldg(ei + (size_t)(p * 2 + 1) * E + e);
    int pos = atomicAdd(cnt + (size_t)p * M + d, 1);
    adj[(size_t)p * E + pos] = s;
}

// ---------------- relation-fused mma.sync GEMM, register epilogue -------------
// C[M, NREL*BN]: for each rel, C[:, rel*BN:] = scale_rel * (A @ B_rel)
// BM=128, 256 threads = 8 warps as 4x2 grid; warp tile 32 x (BN/2).
// A (hi+lo) staged once in smem; B double-buffered via cp.async.
#define A_ST 136                 // A smem stride (bf16 elems); 272B rows: 4-bank advance

template<int BN, bool SCALE>
__global__ __launch_bounds__(256, 2)
void gemm_fused(const __nv_bfloat16* __restrict__ Ahi,
                const __nv_bfloat16* __restrict__ Alo,
                const __nv_bfloat16* __restrict__ Bhi,   // [NREL][128][BN]
                const __nv_bfloat16* __restrict__ Blo,
                const float* __restrict__ rsbase,        // rs_rel = rsbase + rel*2*M
                __half* __restrict__ C, int M) {
    constexpr int LDC = NREL * BN;
    constexpr int BST = BN + 8;
    constexpr int KCH = 4;                    // 128 / 32
    constexpr int TOT = NREL * KCH;
    constexpr int BXF = 32 * BN / 8;          // 16B xfers per (hi|lo) B chunk
    constexpr int WNT = BN / 2 / 8;           // n8 tiles per warp (8 or 4)

    extern __shared__ __align__(16) char dsm[];
    __nv_bfloat16* sAhi = reinterpret_cast<__nv_bfloat16*>(dsm);
    __nv_bfloat16* sAlo = sAhi + 128 * A_ST;
    __nv_bfloat16* sB   = sAlo + 128 * A_ST;  // [2 stages][hi,lo][32*BST]

    const int tid  = threadIdx.x;
    const int w    = tid >> 5;
    const int lane = tid & 31;
    const int warp_row = w & 3;               // 4 rows
    const int warp_col = w >> 2;              // 2 cols
    const int m_off = warp_row * 32;
    const int n_off = warp_col * (BN / 2);
    const int row0 = blockIdx.x * 128;

    const uint32_t saHi = (uint32_t)__cvta_generic_to_shared(sAhi);
    const uint32_t saLo = (uint32_t)__cvta_generic_to_shared(sAlo);
    const uint32_t sb0  = (uint32_t)__cvta_generic_to_shared(sB);

    // ---- A: one-time cp.async load (hi + lo); OOB rows zero-filled ----------
    #pragma unroll
    for (int i = 0; i < 8; i++) {
        int slot = tid + i * 256;
        int r = slot >> 4;
        int c = (slot & 15) * 8;
        int gr = row0 + r;
        bool valid = gr < M;
        const __nv_bfloat16* gh = Ahi + (size_t)gr * 128 + c;
        const __nv_bfloat16* gl = Alo + (size_t)gr * 128 + c;
        cpa16(sAhi + r * A_ST + c, valid ? gh : (const void*)Ahi, valid);
        cpa16(sAlo + r * A_ST + c, valid ? gl : (const void*)Alo, valid);
    }

    auto loadB = [&](int it, int st) {
        int rel = it / KCH;
        int kc = (it % KCH) * 32;
        __nv_bfloat16* dh = sB + st * 2 * 32 * BST;
        __nv_bfloat16* dl = dh + 32 * BST;
        const __nv_bfloat16* gh = Bhi + (size_t)rel * 128 * BN;
        const __nv_bfloat16* gl = Blo + (size_t)rel * 128 * BN;
        #pragma unroll
        for (int i = 0; i < BXF / 256; i++) {
            int slot = tid + i * 256;
            int r = slot / (BN / 8);
            int c = (slot % (BN / 8)) * 8;
            cpa16(dh + r * BST + c, gh + (size_t)(kc + r) * BN + c, true);
            cpa16(dl + r * BST + c, gl + (size_t)(kc + r) * BN + c, true);
        }
    };
    loadB(0, 0);
    cpa_commit();

    float acc[2][WNT][4];
    #pragma unroll
    for (int mt = 0; mt < 2; mt++)
        #pragma unroll
        for (int nt = 0; nt < WNT; nt++)
            #pragma unroll
            for (int k = 0; k < 4; k++) acc[mt][nt][k] = 0.0f;

    // lane-fixed address components
    const int aRow = (lane & 15);             // + m_off + mt*16
    const int aCol = (lane >> 4) * 8;         // + kpos
    const int bRow = (lane & 7) + ((lane >> 3) & 1) * 8;   // + kpos
    const int bCol = (lane >> 4) * 8;         // + n_off + ng*16

    for (int it = 0; it < TOT; it++) {
        cpa_wait0();
        __syncthreads();
        if (it + 1 < TOT) { loadB(it + 1, (it + 1) & 1); cpa_commit(); }

        const uint32_t sbh = sb0 + (uint32_t)((it & 1) * 2 * 32 * BST) * 2;
        const uint32_t sbl = sbh + 32 * BST * 2;
        const int kc = (it % KCH) * 32;

        #pragma unroll
        for (int ks = 0; ks < 32; ks += 16) {
            const int kpos = kc + ks;
            // B fragments: hi + lo, WNT n8-tiles (x4.trans covers 2 tiles)
            uint32_t bhi[WNT][2], blo[WNT][2];
            #pragma unroll
            for (int g = 0; g < WNT / 2; g++) {
                uint32_t t[4];
                uint32_t boff = (uint32_t)((ks + bRow) * BST + n_off + g * 16 + bCol) * 2;
                ldsm_x4t(t, sbh + boff);
                bhi[2 * g][0] = t[0]; bhi[2 * g][1] = t[1];
                bhi[2 * g + 1][0] = t[2]; bhi[2 * g + 1][1] = t[3];
                ldsm_x4t(t, sbl + boff);
                blo[2 * g][0] = t[0]; blo[2 * g][1] = t[1];
                blo[2 * g + 1][0] = t[2]; blo[2 * g + 1][1] = t[3];
            }
            #pragma unroll
            for (int mt = 0; mt < 2; mt++) {
                uint32_t ahi[4], alo[4];
                uint32_t aoff = (uint32_t)((m_off + mt * 16 + aRow) * A_ST + kpos + aCol) * 2;
                ldsm_x4(ahi, saHi + aoff);
                ldsm_x4(alo, saLo + aoff);
                #pragma unroll
                for (int nt = 0; nt < WNT; nt++) {
                    mma16816(acc[mt][nt], ahi, bhi[nt]);
                    mma16816(acc[mt][nt], ahi, blo[nt]);
                    mma16816(acc[mt][nt], alo, bhi[nt]);
                }
            }
        }

        if ((it % KCH) == KCH - 1) {
            // register epilogue for relation rel: scale rows, pack fp16, STG.32
            int rel = it / KCH;
            const float* rs = rsbase + (size_t)rel * 2 * M;
            #pragma unroll
            for (int mt = 0; mt < 2; mt++) {
                int r0 = row0 + m_off + mt * 16 + (lane >> 2);
                int r1 = r0 + 8;
                float s0 = 1.0f, s1 = 1.0f;
                if (SCALE) {
                    if (r0 < M) s0 = __ldg(rs + r0);
                    if (r1 < M) s1 = __ldg(rs + r1);
                }
                #pragma unroll
                for (int nt = 0; nt < WNT; nt++) {
                    int c = rel * BN + n_off + nt * 8 + (lane & 3) * 2;
                    if (r0 < M) {
                        __half2 p = __floats2half2_rn(acc[mt][nt][0] * s0, acc[mt][nt][1] * s0);
                        *reinterpret_cast<uint32_t*>(C + (size_t)r0 * LDC + c) =
                            *reinterpret_cast<uint32_t*>(&p);
                    }
                    if (r1 < M) {
                        __half2 p = __floats2half2_rn(acc[mt][nt][2] * s1, acc[mt][nt][3] * s1);
                        *reinterpret_cast<uint32_t*>(C + (size_t)r1 * LDC + c) =
                            *reinterpret_cast<uint32_t*>(&p);
                    }
                    #pragma unroll
                    for (int k = 0; k < 4; k++) acc[mt][nt][k] = 0.0f;
                }
            }
        }
    }
}

// ---------------- fused 3-relation gathers ------------------------------------
__global__ __launch_bounds__(256)
void gatherL1(const __half* __restrict__ z3,
              __nv_bfloat16* __restrict__ ahi, __nv_bfloat16* __restrict__ alo,
              const int* __restrict__ off, const int* __restrict__ degi,
              const int* __restrict__ adj, const float* __restrict__ degf,
              const float* __restrict__ b1, int M, int E) {
    int w = (blockIdx.x * blockDim.x + threadIdx.x) >> 5;
    if (w >= M) return;
    int lane = threadIdx.x & 31;
    float4 tot = make_float4(0.f, 0.f, 0.f, 0.f);

    #pragma unroll
    for (int r = 0; r < NREL; r++) {
        const int*   offp  = off  + (size_t)r * M;
        const int*   degp  = degi + (size_t)(r * 2 + 1) * M;
        const int*   adjp  = adj  + (size_t)r * E;
        const float* rsout = degf + (size_t)(r * 2 + 0) * M;
        const float* rsin  = degf + (size_t)(r * 2 + 1) * M;
        int st = __ldg(offp + w);
        int len = __ldg(degp + w);
        float4 acc = make_float4(0.f, 0.f, 0.f, 0.f);
        const __half* zr = z3 + (size_t)r * 128;
        int j = 0;
        for (; j + 1 < len; j += 2) {
            int s0 = __ldg(adjp + st + j);
            int s1 = __ldg(adjp + st + j + 1);
            float c0 = __ldg(rsout + s0);
            float c1 = __ldg(rsout + s1);
            uint2 r0 = __ldg(reinterpret_cast<const uint2*>(zr + (size_t)s0 * 384 + lane * 4));
            uint2 r1 = __ldg(reinterpret_cast<const uint2*>(zr + (size_t)s1 * 384 + lane * 4));
            float2 a = __half22float2(*reinterpret_cast<__half2*>(&r0.x));
            float2 b = __half22float2(*reinterpret_cast<__half2*>(&r0.y));
            float2 c2 = __half22float2(*reinterpret_cast<__half2*>(&r1.x));
            float2 d2 = __half22float2(*reinterpret_cast<__half2*>(&r1.y));
            acc.x += c0 * a.x + c1 * c2.x; acc.y += c0 * a.y + c1 * c2.y;
            acc.z += c0 * b.x + c1 * d2.x; acc.w += c0 * b.y + c1 * d2.y;
        }
        if (j < len) {
            int s0 = __ldg(adjp + st + j);
            float c0 = __ldg(rsout + s0);
            uint2 r0 = __ldg(reinterpret_cast<const uint2*>(zr + (size_t)s0 * 384 + lane * 4));
            float2 a = __half22float2(*reinterpret_cast<__half2*>(&r0.x));
            float2 b = __half22float2(*reinterpret_cast<__half2*>(&r0.y));
            acc.x += c0 * a.x; acc.y += c0 * a.y;
            acc.z += c0 * b.x; acc.w += c0 * b.y;
        }
        float ci = __ldg(rsin + w);
        tot.x += ci * acc.x; tot.y += ci * acc.y;
        tot.z += ci * acc.z; tot.w += ci * acc.w;
    }

    int col = lane * 4;
    tot.x = fmaxf(tot.x + __ldg(b1 + col + 0) + __ldg(b1 + 128 + col + 0) + __ldg(b1 + 256 + col + 0), 0.f);
    tot.y = fmaxf(tot.y + __ldg(b1 + col + 1) + __ldg(b1 + 128 + col + 1) + __ldg(b1 + 256 + col + 1), 0.f);
    tot.z = fmaxf(tot.z + __ldg(b1 + col + 2) + __ldg(b1 + 128 + col + 2) + __ldg(b1 + 256 + col + 2), 0.f);
    tot.w = fmaxf(tot.w + __ldg(b1 + col + 3) + __ldg(b1 + 128 + col + 3) + __ldg(b1 + 256 + col + 3), 0.f);

    __nv_bfloat16 hx = __float2bfloat16(tot.x), hy = __float2bfloat16(tot.y);
    __nv_bfloat16 hz = __float2bfloat16(tot.z), hw = __float2bfloat16(tot.w);
    __nv_bfloat16 lx = __float2bfloat16(tot.x - __bfloat162float(hx));
    __nv_bfloat16 ly = __float2bfloat16(tot.y - __bfloat162float(hy));
    __nv_bfloat16 lz = __float2bfloat16(tot.z - __bfloat162float(hz));
    __nv_bfloat16 lw = __float2bfloat16(tot.w - __bfloat162float(hw));
    __nv_bfloat162 h0 = __nv_bfloat162(hx, hy), h1 = __nv_bfloat162(hz, hw);
    __nv_bfloat162 l0 = __nv_bfloat162(lx, ly), l1 = __nv_bfloat162(lz, lw);
    uint2 oh, ol;
    oh.x = *reinterpret_cast<uint32_t*>(&h0); oh.y = *reinterpret_cast<uint32_t*>(&h1);
    ol.x = *reinterpret_cast<uint32_t*>(&l0); ol.y = *reinterpret_cast<uint32_t*>(&l1);
    *reinterpret_cast<uint2*>(ahi + (size_t)w * 128 + col) = oh;
    *reinterpret_cast<uint2*>(alo + (size_t)w * 128 + col) = ol;
}

__global__ __launch_bounds__(256)
void gatherL2(const __half* __restrict__ z3, float* __restrict__ out,
              const int* __restrict__ off, const int* __restrict__ degi,
              const int* __restrict__ adj, const float* __restrict__ degf,
              const float* __restrict__ b2, int M, int E) {
    int w = (blockIdx.x * blockDim.x + threadIdx.x) >> 5;
    if (w >= M) return;
    int lane = threadIdx.x & 31;
    float2 tot = make_float2(0.f, 0.f);

    #pragma unroll
    for (int r = 0; r < NREL; r++) {
        int p = NREL + r;
        const int*   offp  = off  + (size_t)p * M;
        const int*   degp  = degi + (size_t)(p * 2 + 1) * M;
        const int*   adjp  = adj  + (size_t)p * E;
        const float* rsin  = degf + (size_t)(p * 2 + 1) * M;
        int st = __ldg(offp + w);
        int len = __ldg(degp + w);
        float2 acc = make_float2(0.f, 0.f);
        const __half* zr = z3 + (size_t)r * 64;
        int j = 0;
        for (; j + 1 < len; j += 2) {
            int s0 = __ldg(adjp + st + j);
            int s1 = __ldg(adjp + st + j + 1);
            uint32_t r0 = __ldg(reinterpret_cast<const uint32_t*>(zr + (size_t)s0 * 192 + lane * 2));
            uint32_t r1 = __ldg(reinterpret_cast<const uint32_t*>(zr + (size_t)s1 * 192 + lane * 2));
            float2 a = __half22float2(*reinterpret_cast<__half2*>(&r0));
            float2 b = __half22float2(*reinterpret_cast<__half2*>(&r1));
            acc.x += a.x + b.x; acc.y += a.y + b.y;
        }
        if (j < len) {
            int s0 = __ldg(adjp + st + j);
            uint32_t r0 = __ldg(reinterpret_cast<const uint32_t*>(zr + (size_t)s0 * 192 + lane * 2));
            float2 a = __half22float2(*reinterpret_cast<__half2*>(&r0));
            acc.x += a.x; acc.y += a.y;
        }
        float ci = __ldg(rsin + w);
        tot.x += ci * acc.x; tot.y += ci * acc.y;
    }

    int col = lane * 2;
    tot.x += __ldg(b2 + col + 0) + __ldg(b2 + 64 + col + 0) + __ldg(b2 + 128 + col + 0);
    tot.y += __ldg(b2 + col + 1) + __ldg(b2 + 64 + col + 1) + __ldg(b2 + 128 + col + 1);
    *reinterpret_cast<float2*>(out + (size_t)w * 64 + col) = tot;
}

// ---------------- orchestration ----------------------------------------------
extern "C" void kernel_launch(void* const* d_in, const int* in_sizes, int n_in,
                              void* d_out, int out_size) {
    const float* x  = (const float*)d_in[0];
    const float* W1 = (const float*)d_in[1];
    const float* b1 = (const float*)d_in[2];
    const float* W2 = (const float*)d_in[3];
    const float* b2 = (const float*)d_in[4];
    const int*   ei = (const int*)d_in[5];
    float* out = (float*)d_out;

    const int M = in_sizes[0] / DIN;
    const int E = in_sizes[5] / (2 * NREL * 2);

    float* degf;
    __half* z3;
    __nv_bfloat16 *ahi, *alo, *w1hi, *w1lo, *w2hi, *w2lo;
    int *degi, *off, *cnt, *adj, *bsum;
    cudaGetSymbolAddress((void**)&z3,   g_z3);
    cudaGetSymbolAddress((void**)&ahi,  g_ahi);
    cudaGetSymbolAddress((void**)&alo,  g_alo);
    cudaGetSymbolAddress((void**)&w1hi, g_w1hi);
    cudaGetSymbolAddress((void**)&w1lo, g_w1lo);
    cudaGetSymbolAddress((void**)&w2hi, g_w2hi);
    cudaGetSymbolAddress((void**)&w2lo, g_w2lo);
    cudaGetSymbolAddress((void**)&degf, g_degf);
    cudaGetSymbolAddress((void**)&degi, g_degi);
    cudaGetSymbolAddress((void**)&off,  g_off);
    cudaGetSymbolAddress((void**)&cnt,  g_cnt);
    cudaGetSymbolAddress((void**)&adj,  g_adj);
    cudaGetSymbolAddress((void**)&bsum, g_bsum);

    const int TB = 256;
    auto blocks = [](long n, int tb) { return (int)((n + tb - 1) / tb); };
    const int nblk_scan = (M + SCAN_CHUNK - 1) / SCAN_CHUNK;
    const int gemm_grid = (M + 127) / 128;
    const int gw = blocks((long)M * 32, TB);

    // dynamic smem: A(69632) + B(2 stages * (hi+lo) * 32*BST*2)
    const int SMEM_L1 = 128 * A_ST * 2 * 2 + 2 * 2 * 32 * (128 + 8) * 2;  // 104448
    const int SMEM_L2 = 128 * A_ST * 2 * 2 + 2 * 2 * 32 * (64 + 8) * 2;   //  88064
    cudaFuncSetAttribute(gemm_fused<128, false>,
                         cudaFuncAttributeMaxDynamicSharedMemorySize, SMEM_L1);
    cudaFuncSetAttribute(gemm_fused<64, true>,
                         cudaFuncAttributeMaxDynamicSharedMemorySize, SMEM_L2);

    // ---- fork side stream for CSR build ---------------------------------------
    cudaStream_t s2;
    cudaStreamCreateWithFlags(&s2, cudaStreamNonBlocking);
    cudaEvent_t evFork, evCsr1, evDeg2, evCsr2;
    cudaEventCreateWithFlags(&evFork, cudaEventDisableTiming);
    cudaEventCreateWithFlags(&evCsr1, cudaEventDisableTiming);
    cudaEventCreateWithFlags(&evDeg2, cudaEventDisableTiming);
    cudaEventCreateWithFlags(&evCsr2, cudaEventDisableTiming);
    cudaEventRecord(evFork, 0);
    cudaStreamWaitEvent(s2, evFork, 0);

    // ---- main: splits + fused layer-1 GEMM (degree-independent) ---------------
    split_kernel<<<blocks((long)M * DIN, TB), TB>>>(x, ahi, alo, M * DIN);
    split_kernel<<<blocks(NREL * DIN * DH, TB), TB>>>(W1, w1hi, w1lo, NREL * DIN * DH);
    split_kernel<<<blocks(NREL * DH * DOUT, TB), TB>>>(W2, w2hi, w2lo, NREL * DH * DOUT);
    gemm_fused<128, false><<<gemm_grid, 256, SMEM_L1>>>(
        ahi, alo, w1hi, w1lo, nullptr, z3, M);

    // ---- side: layer-1 CSR, then layer-2 CSR ----------------------------------
    cudaMemsetAsync(degi, 0, (size_t)12 * M * sizeof(int), s2);
    { dim3 g(blocks(E, TB), 3); count_deg_kernel<<<g, TB, 0, s2>>>(ei, degi, E, M, 0); }
    rsqrt_kernel<<<blocks((long)6 * M, TB), TB, 0, s2>>>(degi, degf, 6 * M);
    { dim3 g(nblk_scan, 3); scanA<<<g, 256, 0, s2>>>(degi, off, bsum, M, 0); }
    scanB<<<3, MAXBLK, 0, s2>>>(bsum, nblk_scan, 0);
    { dim3 g(blocks(M, TB), 3); scanC<<<g, TB, 0, s2>>>(off, cnt, bsum, M, 0); }
    { dim3 g(blocks(E, TB), 3); fill_adj_kernel<<<g, TB, 0, s2>>>(ei, cnt, adj, E, M, 0); }
    cudaEventRecord(evCsr1, s2);
    { dim3 g(blocks(E, TB), 3); count_deg_kernel<<<g, TB, 0, s2>>>(ei, degi, E, M, 3); }
    rsqrt_kernel<<<blocks((long)6 * M, TB), TB, 0, s2>>>(degi + (size_t)6 * M, degf + (size_t)6 * M, 6 * M);
    cudaEventRecord(evDeg2, s2);
    { dim3 g(nblk_scan, 3); scanA<<<g, 256, 0, s2>>>(degi, off, bsum, M, 3); }
    scanB<<<3, MAXBLK, 0, s2>>>(bsum, nblk_scan, 3);
    { dim3 g(blocks(M, TB), 3); scanC<<<g, TB, 0, s2>>>(off, cnt, bsum, M, 3); }
    { dim3 g(blocks(E, TB), 3); fill_adj_kernel<<<g, TB, 0, s2>>>(ei, cnt, adj, E, M, 3); }
    cudaEventRecord(evCsr2, s2);

    // ---- join: gatherL1 -> layer-2 GEMM -> gatherL2 ----------------------------
    cudaStreamWaitEvent(0, evCsr1, 0);
    gatherL1<<<gw, TB>>>(z3, ahi, alo, off, degi, adj, degf, b1, M, E);

    cudaStreamWaitEvent(0, evDeg2, 0);
    gemm_fused<64, true><<<gemm_grid, 256, SMEM_L2>>>(
        ahi, alo, w2hi, w2lo, degf + (size_t)6 * M, z3, M);

    cudaStreamWaitEvent(0, evCsr2, 0);
    gatherL2<<<gw, TB>>>(z3, out, off, degi, adj, degf, b2, M, E);

    cudaStreamDestroy(s2);
    cudaEventDestroy(evFork);
    cudaEventDestroy(evCsr1);
    cudaEventDestroy(evDeg2);
    cudaEventDestroy(evCsr2);
}